// round 10
// baseline (speedup 1.0000x reference)
#include <cuda_runtime.h>
#include <math.h>

#define N       300
#define NM      9
#define BATCH   131072
#define NLAYERS 5
#define KTAP    10
#define TAPS    (2*KTAP + 1)   // 21
#define TBL12   384            // stride-12 table: row m occupies [m*384 + 12L + t]
#define WARPS   8
#define RPW     8              // row-PAIRS per warp
#define NPAIRS  (BATCH / 2)
#define FULLMASK 0xffffffffu

static __device__ double g_cfull[NLAYERS][N];
static __device__ float  g_G[NLAYERS][NM * N];
static __device__ float  g_At[NM * TBL12];           // A[m][j]
static __device__ float  g_Gt[NLAYERS][NM * TBL12];  // Ghat = A * Chat^-1 (TRUNCATED taps)
static __device__ float  g_Hn[NLAYERS][NM * TBL12];  // NEGATED H (exact G)
static __device__ float  g_ct[NLAYERS][24];          // conv taps ct[i]=c[|i-10|]
static __device__ float  g_scal[NLAYERS][8];

// ---------------------------------------------------------------------------
// packed f32x2 + warp helpers (sm_103a)
// ---------------------------------------------------------------------------
__device__ __forceinline__ float2 f2fma(float2 a, float2 b, float2 c) {
    unsigned long long ra = reinterpret_cast<unsigned long long&>(a);
    unsigned long long rb = reinterpret_cast<unsigned long long&>(b);
    unsigned long long rc = reinterpret_cast<unsigned long long&>(c);
    unsigned long long rd;
    asm("fma.rn.f32x2 %0, %1, %2, %3;" : "=l"(rd) : "l"(ra), "l"(rb), "l"(rc));
    return reinterpret_cast<float2&>(rd);
}
__device__ __forceinline__ float2 f2add(float2 a, float2 b) {
    unsigned long long ra = reinterpret_cast<unsigned long long&>(a);
    unsigned long long rb = reinterpret_cast<unsigned long long&>(b);
    unsigned long long rd;
    asm("add.rn.f32x2 %0, %1, %2;" : "=l"(rd) : "l"(ra), "l"(rb));
    return reinterpret_cast<float2&>(rd);
}
__device__ __forceinline__ float2 f2mul(float2 a, float2 b) {
    unsigned long long ra = reinterpret_cast<unsigned long long&>(a);
    unsigned long long rb = reinterpret_cast<unsigned long long&>(b);
    unsigned long long rd;
    asm("mul.rn.f32x2 %0, %1, %2;" : "=l"(rd) : "l"(ra), "l"(rb));
    return reinterpret_cast<float2&>(rd);
}
__device__ __forceinline__ float2 dup(float s) { return make_float2(s, s); }
__device__ __forceinline__ float2 shfl2(float2 v, int src) {
    float2 r;
    r.x = __shfl_sync(FULLMASK, v.x, src);
    r.y = __shfl_sync(FULLMASK, v.y, src);
    return r;
}
__device__ __forceinline__ float2 bfly_sum(float2 v) {
    #pragma unroll
    for (int off = 16; off >= 1; off >>= 1) {
        float sx = __shfl_xor_sync(FULLMASK, v.x, off);
        float sy = __shfl_xor_sync(FULLMASK, v.y, off);
        v = f2add(v, make_float2(sx, sy));
    }
    return v;
}
__device__ __forceinline__ float softt(float v, float lam) {
    return copysignf(fmaxf(fabsf(v) - lam, 0.f), v);
}

// ---------------------------------------------------------------------------
__global__ void pre_A_kernel(const float* __restrict__ A) {
    int idx = blockIdx.x * blockDim.x + threadIdx.x;
    if (idx < NM * TBL12) {
        int m = idx / TBL12, ii = idx % TBL12;
        int L = ii / 12, t = ii % 12;
        int j = L * 10 + t;
        g_At[idx] = (t < 10 && j < N) ? A[m * N + j] : 0.0f;
    }
}

// ---------------------------------------------------------------------------
__global__ void pre_layer_kernel(const float* __restrict__ A,
                                 const float* __restrict__ gamma_tv,
                                 const float* __restrict__ lambda_tv,
                                 const float* __restrict__ alpha) {
    const double PI = 3.14159265358979323846;
    int l = blockIdx.x;
    int tid = threadIdx.x;
    double g = (double)gamma_tv[l], al = (double)alpha[l];

    __shared__ double costab[N];
    __shared__ double invlam[N];
    for (int m = tid; m < N; m += blockDim.x) {
        double th = 2.0 * PI * (double)m / (double)N;
        costab[m] = cos(th);
        invlam[m] = 1.0 / (al + 2.0 * g - 2.0 * g * costab[m]);
    }
    __syncthreads();

    for (int k = tid; k < N; k += blockDim.x) {
        double s = 0.0;
        int mk = 0;
        for (int m = 0; m < N; m++) {
            s += costab[mk] * invlam[m];
            mk += k; if (mk >= N) mk -= N;
        }
        g_cfull[l][k] = s / (double)N;
    }
    __syncthreads();

    // exact G (for S9 and H)
    for (int idx = tid; idx < NM * N; idx += blockDim.x) {
        int m = idx / N, j = idx % N;
        float s = 0.f;
        for (int t = 0; t < N; t++) {
            int d = j - t; if (d < 0) d += N;
            s += A[m * N + t] * (float)g_cfull[l][d];
        }
        g_G[l][m * N + j] = s;
    }
    __syncthreads();

    __shared__ double S9[81], S9i[81];
    for (int idx = tid; idx < 81; idx += blockDim.x) {
        int p = idx / 9, q = idx % 9;
        double s = (p == q) ? 1.0 : 0.0;
        for (int j = 0; j < N; j++)
            s += (double)g_G[l][p * N + j] * (double)A[q * N + j];
        S9[idx] = s;
    }
    __syncthreads();

    if (tid == 0) {
        for (int i = 0; i < 81; i++) S9i[i] = ((i / 9) == (i % 9)) ? 1.0 : 0.0;
        for (int col = 0; col < 9; col++) {
            int piv = col; double best = fabs(S9[col * 9 + col]);
            for (int rr = col + 1; rr < 9; rr++) {
                double v = fabs(S9[rr * 9 + col]);
                if (v > best) { best = v; piv = rr; }
            }
            if (piv != col) {
                for (int c2 = 0; c2 < 9; c2++) {
                    double tmp = S9[col * 9 + c2]; S9[col * 9 + c2] = S9[piv * 9 + c2]; S9[piv * 9 + c2] = tmp;
                    tmp = S9i[col * 9 + c2]; S9i[col * 9 + c2] = S9i[piv * 9 + c2]; S9i[piv * 9 + c2] = tmp;
                }
            }
            double d = 1.0 / S9[col * 9 + col];
            for (int c2 = 0; c2 < 9; c2++) { S9[col * 9 + c2] *= d; S9i[col * 9 + c2] *= d; }
            for (int rr = 0; rr < 9; rr++) {
                if (rr == col) continue;
                double f = S9[rr * 9 + col];
                for (int c2 = 0; c2 < 9; c2++) {
                    S9[rr * 9 + c2]  -= f * S9[col * 9 + c2];
                    S9i[rr * 9 + c2] -= f * S9i[col * 9 + c2];
                }
            }
        }
    }
    __syncthreads();

    // Ghat (TRUNCATED taps, matches the runtime conv operator exactly) and Hn
    for (int idx = tid; idx < NM * TBL12; idx += blockDim.x) {
        int m = idx / TBL12, ii = idx % TBL12;
        int L = ii / 12, t = ii % 12;
        int j = L * 10 + t;
        float sg = 0.f, sh = 0.f;
        if (t < 10 && j < N) {
            for (int tt = 0; tt < N; tt++) {
                int d = j - tt; if (d < 0) d += N;
                int dd = d < N - d ? d : N - d;       // circular distance
                if (dd <= KTAP)
                    sg += A[m * N + tt] * (float)g_cfull[l][d];
            }
            for (int q = 0; q < NM; q++)
                sh -= (float)S9i[m * 9 + q] * g_G[l][q * N + j];
        }
        g_Gt[l][idx] = sg;
        g_Hn[l][idx] = sh;
    }
    for (int i = tid; i < 24; i += blockDim.x) {
        float v = 0.f;
        if (i < TAPS) { int d = i - KTAP; if (d < 0) d = -d; v = (float)g_cfull[l][d]; }
        g_ct[l][i] = v;
    }
    if (tid == 0) {
        g_scal[l][0] = (float)g;
        g_scal[l][1] = (float)al;
        g_scal[l][2] = (float)((double)lambda_tv[l] / g);
        g_scal[l][3] = (float)(1.0 / g);
        g_scal[l][4] = (float)(1.0 / al);
    }
}

// ---------------------------------------------------------------------------
// Main fused kernel: 8 warps, state in registers, 1 block/SM.
// pd computed from r via TRUNCATED Ghat (numerics == computing from y via A,
// but data-independent of the conv so the butterfly overlaps the conv chain).
// 21-tap conv (KTAP=10), conv code identical to the 897us R7 kernel.
// Lane L (0..29) owns elements j = 10L..10L+9.
// ---------------------------------------------------------------------------
__global__ void __launch_bounds__(WARPS * 32)
ladmm_main(const float* __restrict__ b, float* __restrict__ out) {
    extern __shared__ float sm[];
    float*  sA    = sm;                                   // NM*TBL12
    float*  sG    = sA + NM * TBL12;                      // 5*NM*TBL12
    float*  sHn   = sG + NLAYERS * NM * TBL12;            // 5*NM*TBL12
    float2* sct2  = (float2*)(sHn + NLAYERS * NM * TBL12);// 5*24 float2
    float*  sscal = (float*)(sct2 + NLAYERS * 24);        // 40
    float*  stage = sscal + 40;                           // WARPS*608

    int tid = threadIdx.x;
    for (int i = tid; i < NM * TBL12; i += WARPS * 32) sA[i] = g_At[i];
    for (int i = tid; i < NLAYERS * NM * TBL12; i += WARPS * 32) {
        sG[i]  = (&g_Gt[0][0])[i];
        sHn[i] = (&g_Hn[0][0])[i];
    }
    for (int i = tid; i < NLAYERS * 24; i += WARPS * 32) {
        float v = (&g_ct[0][0])[i];
        sct2[i] = make_float2(v, v);
    }
    for (int i = tid; i < NLAYERS * 8; i += WARPS * 32) sscal[i] = (&g_scal[0][0])[i];
    __syncthreads();

    int wid = tid >> 5, lane = tid & 31;
    int base12 = lane * 12;
    int j0 = lane * 10;
    int lm1 = (lane + 29) % 30;
    int lp1 = (lane + 1) % 30;

    const float2 neg1 = make_float2(-1.f, -1.f);
    float* wstage = stage + wid * 608;

    #pragma unroll 1
    for (int rit = 0; rit < RPW; rit++) {
        int pairIdx = blockIdx.x * (WARPS * RPW) + wid * RPW + rit;
        size_t row0 = (size_t)pairIdx * 2;

        // --- b rows -> bm[m] packed pairs
        float bv = (lane < 2 * NM) ? b[(size_t)pairIdx * (2 * NM) + lane] : 0.f;
        float2 bm[9];
        #pragma unroll
        for (int m = 0; m < 9; m++)
            bm[m] = make_float2(__shfl_sync(FULLMASK, bv, m),
                                __shfl_sync(FULLMASK, bv, 9 + m));

        // --- bA[t] = sum_m bm[m]*A[m][j0+t]
        float2 bA[10];
        #pragma unroll
        for (int t = 0; t < 10; t++) bA[t] = make_float2(0.f, 0.f);
        #pragma unroll
        for (int m = 0; m < 9; m++) {
            const float4* rA = reinterpret_cast<const float4*>(sA + m * TBL12 + base12);
            float4 q0 = rA[0], q1 = rA[1], q2 = rA[2];
            float av[10] = {q0.x,q0.y,q0.z,q0.w,q1.x,q1.y,q1.z,q1.w,q2.x,q2.y};
            #pragma unroll
            for (int t = 0; t < 10; t++)
                bA[t] = f2fma(bm[m], dup(av[t]), bA[t]);
        }

        float2 x[10], eta[10], tau[10];
        #pragma unroll
        for (int t = 0; t < 10; t++) {
            x[t] = make_float2(1.f, 1.f);
            eta[t] = make_float2(0.f, 0.f);
            tau[t] = make_float2(0.f, 0.f);
        }

        #pragma unroll 1
        for (int l = 0; l < NLAYERS; l++) {
            const float* sc = sscal + l * 8;
            float gs = sc[0], als = sc[1], lamg = sc[2], invgs = sc[3], invals = sc[4];
            float2 g2 = dup(gs), al2 = dup(als), invg2 = dup(invgs), inval2 = dup(invals);
            const float2* ctab = sct2 + l * 24;
            const float* sGl = sG + l * (NM * TBL12);
            const float* sHl = sHn + l * (NM * TBL12);

            // --- residual r = bA + al*w - tau + g*u - eta
            float2 xm1 = shfl2(x[9], lm1);
            float2 r[10];
            #pragma unroll
            for (int t = 0; t < 10; t++) {
                float2 xp = (t == 0) ? xm1 : x[t - 1];
                float2 v = f2fma(neg1, x[t], xp);
                v = f2fma(eta[t], invg2, v);
                float2 u; u.x = softt(v.x, lamg); u.y = softt(v.y, lamg);
                float2 w = f2fma(tau[t], inval2, x[t]);
                w.x = fmaxf(w.x, 0.f); w.y = fmaxf(w.y, 0.f);
                float2 s = f2fma(neg1, tau[t], bA[t]);
                s = f2fma(al2, w, s);
                s = f2fma(g2, u, s);
                r[t] = f2fma(neg1, eta[t], s);
            }

            // --- pd[m] = sum_j r_j Ghat[m][j]  (independent of the conv:
            //     butterfly SHFL chain overlaps the conv FMA chain)
            float2 pd[9];
            #pragma unroll
            for (int m = 0; m < 9; m++) {
                const float4* rG = reinterpret_cast<const float4*>(sGl + m * TBL12 + base12);
                float4 q0 = rG[0], q1 = rG[1], q2 = rG[2];
                float gv[10] = {q0.x,q0.y,q0.z,q0.w,q1.x,q1.y,q1.z,q1.w,q2.x,q2.y};
                float2 acc = f2mul(r[0], dup(gv[0]));
                #pragma unroll
                for (int t = 1; t < 10; t++)
                    acc = f2fma(r[t], dup(gv[t]), acc);
                pd[m] = acc;
            }
            #pragma unroll
            for (int m = 0; m < 9; m++) pd[m] = bfly_sum(pd[m]);

            // --- y = C^-1 r : 21-tap circulant conv (R7-identical)
            float2 y[10];
            float2 wchunk[10];
            #pragma unroll
            for (int k = 0; k < 10; k++) wchunk[k] = shfl2(r[k], lm1);
            {
                float2 c0 = ctab[0];
                #pragma unroll
                for (int t = 0; t < 10; t++) y[t] = f2mul(c0, wchunk[t]);
            }
            #pragma unroll
            for (int d = 1; d < 10; d++) {
                float2 cd = ctab[d];
                #pragma unroll
                for (int t = 0; t < 10; t++)
                    if (t + d < 10) y[t] = f2fma(cd, wchunk[t + d], y[t]);
            }
            #pragma unroll
            for (int i = 1; i < 20; i++) {
                float2 ci = ctab[i];
                #pragma unroll
                for (int t = 0; t < 10; t++) {
                    int k = t + i - 10;
                    if (k >= 0 && k < 10) y[t] = f2fma(ci, r[k], y[t]);
                }
            }
            #pragma unroll
            for (int k = 0; k < 10; k++) wchunk[k] = shfl2(r[k], lp1);
            #pragma unroll
            for (int i = 11; i < 21; i++) {
                float2 ci = ctab[i];
                #pragma unroll
                for (int t = 0; t < 10; t++) {
                    int k = t + i - 20;
                    if (k >= 0 && k < 10) y[t] = f2fma(ci, wchunk[k], y[t]);
                }
            }

            // --- xn = y + sum_m pd[m] * Hn[m][j]
            float2 xn[10];
            #pragma unroll
            for (int t = 0; t < 10; t++) xn[t] = y[t];
            #pragma unroll
            for (int m = 0; m < 9; m++) {
                const float4* rH = reinterpret_cast<const float4*>(sHl + m * TBL12 + base12);
                float4 q0 = rH[0], q1 = rH[1], q2 = rH[2];
                float hv[10] = {q0.x,q0.y,q0.z,q0.w,q1.x,q1.y,q1.z,q1.w,q2.x,q2.y};
                #pragma unroll
                for (int t = 0; t < 10; t++)
                    xn[t] = f2fma(pd[m], dup(hv[t]), xn[t]);
            }

            // --- dual updates (recompute u,w from OLD state)
            float2 xnm1 = shfl2(xn[9], lm1);
            float2 xprev_old = xm1;
            #pragma unroll
            for (int t = 0; t < 10; t++) {
                float2 xp = xprev_old;
                xprev_old = x[t];
                float2 xnp = (t == 0) ? xnm1 : xn[t - 1];
                float2 v = f2fma(neg1, x[t], xp);
                v = f2fma(eta[t], invg2, v);
                float2 u; u.x = softt(v.x, lamg); u.y = softt(v.y, lamg);
                float2 w = f2fma(tau[t], inval2, x[t]);
                w.x = fmaxf(w.x, 0.f); w.y = fmaxf(w.y, 0.f);
                float2 d1 = f2fma(neg1, xn[t], xnp);
                d1 = f2fma(neg1, u, d1);
                eta[t] = f2fma(g2, d1, eta[t]);
                float2 d2 = f2fma(neg1, w, xn[t]);
                tau[t] = f2fma(al2, d2, tau[t]);
                x[t] = xn[t];
            }
        }

        // --- store both rows, coalesced float4 via smem staging
        __syncwarp();
        if (lane < 30) {
            #pragma unroll
            for (int t = 0; t < 10; t++) {
                wstage[j0 + t]       = x[t].x;
                wstage[304 + j0 + t] = x[t].y;
            }
        }
        __syncwarp();
        {
            const float4* st4 = reinterpret_cast<const float4*>(wstage);
            float4* out4 = reinterpret_cast<float4*>(out);
            size_t o0 = row0 * (N / 4);
            for (int idx = lane; idx < N / 4; idx += 32) {
                out4[o0 + idx] = st4[idx];
                out4[o0 + N / 4 + idx] = st4[76 + idx];
            }
        }
        __syncwarp();
    }
}

// ---------------------------------------------------------------------------
extern "C" void kernel_launch(void* const* d_in, const int* in_sizes, int n_in,
                              void* d_out, int out_size) {
    const float* b         = (const float*)d_in[0];
    const float* A         = (const float*)d_in[2];
    const float* gamma_tv  = (const float*)d_in[3];
    const float* lambda_tv = (const float*)d_in[4];
    const float* alpha     = (const float*)d_in[5];
    float* out = (float*)d_out;

    pre_A_kernel<<<(NM * TBL12 + 255) / 256, 256>>>(A);
    pre_layer_kernel<<<NLAYERS, 256>>>(A, gamma_tv, lambda_tv, alpha);

    size_t smembytes = (size_t)(NM * TBL12 * (1 + 2 * NLAYERS)        // 38016
                                + NLAYERS * 24 * 2 + NLAYERS * 8      // 280
                                + WARPS * 608) * sizeof(float);       // 4864 -> ~173KB
    cudaFuncSetAttribute(ladmm_main,
                         cudaFuncAttributeMaxDynamicSharedMemorySize,
                         (int)smembytes);
    int grid = NPAIRS / (WARPS * RPW);
    ladmm_main<<<grid, WARPS * 32, smembytes>>>(b, out);
}

// round 11
// speedup vs baseline: 1.1321x; 1.1321x over previous
#include <cuda_runtime.h>
#include <math.h>

#define N       300
#define NM      9
#define BATCH   131072
#define NLAYERS 5
#define KTAP    10
#define TAPS    (2*KTAP + 1)   // 21
#define TBL12   384            // stride-12 table: row m occupies [m*384 + 12L + t]
#define WARPS   10
#define RPW     8              // row-PAIRS per warp
#define NPAIRS  (BATCH / 2)
#define FULLMASK 0xffffffffu

static __device__ double g_cfull[NLAYERS][N];
static __device__ float  g_G[NLAYERS][NM * N];
static __device__ float  g_At[NM * TBL12];           // A[m][j], j=10L+t at [m*384+12L+t]
static __device__ float  g_Hn[NLAYERS][NM * TBL12];  // NEGATED H, same layout
static __device__ float  g_ct[NLAYERS][24];          // conv taps ct[i]=c[|i-10|]
static __device__ float  g_scal[NLAYERS][8];

// ---------------------------------------------------------------------------
// packed f32x2 + warp helpers (sm_103a)
// ---------------------------------------------------------------------------
__device__ __forceinline__ float2 f2fma(float2 a, float2 b, float2 c) {
    unsigned long long ra = reinterpret_cast<unsigned long long&>(a);
    unsigned long long rb = reinterpret_cast<unsigned long long&>(b);
    unsigned long long rc = reinterpret_cast<unsigned long long&>(c);
    unsigned long long rd;
    asm("fma.rn.f32x2 %0, %1, %2, %3;" : "=l"(rd) : "l"(ra), "l"(rb), "l"(rc));
    return reinterpret_cast<float2&>(rd);
}
__device__ __forceinline__ float2 f2add(float2 a, float2 b) {
    unsigned long long ra = reinterpret_cast<unsigned long long&>(a);
    unsigned long long rb = reinterpret_cast<unsigned long long&>(b);
    unsigned long long rd;
    asm("add.rn.f32x2 %0, %1, %2;" : "=l"(rd) : "l"(ra), "l"(rb));
    return reinterpret_cast<float2&>(rd);
}
__device__ __forceinline__ float2 f2mul(float2 a, float2 b) {
    unsigned long long ra = reinterpret_cast<unsigned long long&>(a);
    unsigned long long rb = reinterpret_cast<unsigned long long&>(b);
    unsigned long long rd;
    asm("mul.rn.f32x2 %0, %1, %2;" : "=l"(rd) : "l"(ra), "l"(rb));
    return reinterpret_cast<float2&>(rd);
}
__device__ __forceinline__ float2 dup(float s) { return make_float2(s, s); }
__device__ __forceinline__ float2 shfl2(float2 v, int src) {
    float2 r;
    r.x = __shfl_sync(FULLMASK, v.x, src);
    r.y = __shfl_sync(FULLMASK, v.y, src);
    return r;
}
__device__ __forceinline__ float2 bfly_sum(float2 v) {
    #pragma unroll
    for (int off = 16; off >= 1; off >>= 1) {
        float sx = __shfl_xor_sync(FULLMASK, v.x, off);
        float sy = __shfl_xor_sync(FULLMASK, v.y, off);
        v = f2add(v, make_float2(sx, sy));
    }
    return v;
}
__device__ __forceinline__ float softt(float v, float lam) {
    return copysignf(fmaxf(fabsf(v) - lam, 0.f), v);
}

// ---------------------------------------------------------------------------
__global__ void pre_A_kernel(const float* __restrict__ A) {
    int idx = blockIdx.x * blockDim.x + threadIdx.x;
    if (idx < NM * TBL12) {
        int m = idx / TBL12, ii = idx % TBL12;
        int L = ii / 12, t = ii % 12;
        int j = L * 10 + t;
        g_At[idx] = (t < 10 && j < N) ? A[m * N + j] : 0.0f;
    }
}

// ---------------------------------------------------------------------------
__global__ void pre_layer_kernel(const float* __restrict__ A,
                                 const float* __restrict__ gamma_tv,
                                 const float* __restrict__ lambda_tv,
                                 const float* __restrict__ alpha) {
    const double PI = 3.14159265358979323846;
    int l = blockIdx.x;
    int tid = threadIdx.x;
    double g = (double)gamma_tv[l], al = (double)alpha[l];

    __shared__ double costab[N];
    __shared__ double invlam[N];
    for (int m = tid; m < N; m += blockDim.x) {
        double th = 2.0 * PI * (double)m / (double)N;
        costab[m] = cos(th);
        invlam[m] = 1.0 / (al + 2.0 * g - 2.0 * g * costab[m]);
    }
    __syncthreads();

    for (int k = tid; k < N; k += blockDim.x) {
        double s = 0.0;
        int mk = 0;
        for (int m = 0; m < N; m++) {
            s += costab[mk] * invlam[m];
            mk += k; if (mk >= N) mk -= N;
        }
        g_cfull[l][k] = s / (double)N;
    }
    __syncthreads();

    for (int idx = tid; idx < NM * N; idx += blockDim.x) {
        int m = idx / N, j = idx % N;
        float s = 0.f;
        for (int t = 0; t < N; t++) {
            int d = j - t; if (d < 0) d += N;
            s += A[m * N + t] * (float)g_cfull[l][d];
        }
        g_G[l][m * N + j] = s;
    }
    __syncthreads();

    __shared__ double S9[81], S9i[81];
    for (int idx = tid; idx < 81; idx += blockDim.x) {
        int p = idx / 9, q = idx % 9;
        double s = (p == q) ? 1.0 : 0.0;
        for (int j = 0; j < N; j++)
            s += (double)g_G[l][p * N + j] * (double)A[q * N + j];
        S9[idx] = s;
    }
    __syncthreads();

    if (tid == 0) {
        for (int i = 0; i < 81; i++) S9i[i] = ((i / 9) == (i % 9)) ? 1.0 : 0.0;
        for (int col = 0; col < 9; col++) {
            int piv = col; double best = fabs(S9[col * 9 + col]);
            for (int rr = col + 1; rr < 9; rr++) {
                double v = fabs(S9[rr * 9 + col]);
                if (v > best) { best = v; piv = rr; }
            }
            if (piv != col) {
                for (int c2 = 0; c2 < 9; c2++) {
                    double tmp = S9[col * 9 + c2]; S9[col * 9 + c2] = S9[piv * 9 + c2]; S9[piv * 9 + c2] = tmp;
                    tmp = S9i[col * 9 + c2]; S9i[col * 9 + c2] = S9i[piv * 9 + c2]; S9i[piv * 9 + c2] = tmp;
                }
            }
            double d = 1.0 / S9[col * 9 + col];
            for (int c2 = 0; c2 < 9; c2++) { S9[col * 9 + c2] *= d; S9i[col * 9 + c2] *= d; }
            for (int rr = 0; rr < 9; rr++) {
                if (rr == col) continue;
                double f = S9[rr * 9 + col];
                for (int c2 = 0; c2 < 9; c2++) {
                    S9[rr * 9 + c2]  -= f * S9[col * 9 + c2];
                    S9i[rr * 9 + c2] -= f * S9i[col * 9 + c2];
                }
            }
        }
    }
    __syncthreads();

    for (int idx = tid; idx < NM * TBL12; idx += blockDim.x) {
        int m = idx / TBL12, ii = idx % TBL12;
        int L = ii / 12, t = ii % 12;
        int j = L * 10 + t;
        float s = 0.f;
        if (t < 10 && j < N) {
            for (int q = 0; q < NM; q++)
                s -= (float)S9i[m * 9 + q] * g_G[l][q * N + j];
        }
        g_Hn[l][idx] = s;
    }
    for (int i = tid; i < 24; i += blockDim.x) {
        float v = 0.f;
        if (i < TAPS) { int d = i - KTAP; if (d < 0) d = -d; v = (float)g_cfull[l][d]; }
        g_ct[l][i] = v;
    }
    if (tid == 0) {
        g_scal[l][0] = (float)g;
        g_scal[l][1] = (float)al;
        g_scal[l][2] = (float)((double)lambda_tv[l] / g);
        g_scal[l][3] = (float)(1.0 / g);
        g_scal[l][4] = (float)(1.0 / al);
    }
}

// ---------------------------------------------------------------------------
// Main fused kernel: R7 structure, 10 warps/block (320 thr) -> 204-reg cap,
// expected spill-free, 10 warps/SM residency.
// Lane L (0..29) owns elements j = 10L..10L+9.
// ---------------------------------------------------------------------------
__global__ void __launch_bounds__(WARPS * 32)
ladmm_main(const float* __restrict__ b, float* __restrict__ out) {
    extern __shared__ float sm[];
    float*  sA    = sm;                                   // NM*TBL12      = 3456
    float*  sHn   = sA + NM * TBL12;                      // 5*NM*TBL12    = 17280
    float2* sct2  = (float2*)(sHn + NLAYERS * NM * TBL12);// 5*24 float2
    float*  sscal = (float*)(sct2 + NLAYERS * 24);        // 40
    float*  stage = sscal + 40;                           // WARPS*608

    int tid = threadIdx.x;
    for (int i = tid; i < NM * TBL12; i += WARPS * 32) sA[i] = g_At[i];
    for (int i = tid; i < NLAYERS * NM * TBL12; i += WARPS * 32) sHn[i] = (&g_Hn[0][0])[i];
    for (int i = tid; i < NLAYERS * 24; i += WARPS * 32) {
        float v = (&g_ct[0][0])[i];
        sct2[i] = make_float2(v, v);
    }
    for (int i = tid; i < NLAYERS * 8; i += WARPS * 32) sscal[i] = (&g_scal[0][0])[i];
    __syncthreads();

    int wid = tid >> 5, lane = tid & 31;
    int base12 = lane * 12;
    int j0 = lane * 10;
    int lm1 = (lane + 29) % 30;
    int lp1 = (lane + 1) % 30;

    const float2 neg1 = make_float2(-1.f, -1.f);
    float* wstage = stage + wid * 608;

    #pragma unroll 1
    for (int rit = 0; rit < RPW; rit++) {
        int pairIdx = blockIdx.x * (WARPS * RPW) + wid * RPW + rit;
        if (pairIdx >= NPAIRS) break;
        size_t row0 = (size_t)pairIdx * 2;

        // --- b rows -> bm[m] packed pairs
        float bv = (lane < 2 * NM) ? b[(size_t)pairIdx * (2 * NM) + lane] : 0.f;
        float2 bm[9];
        #pragma unroll
        for (int m = 0; m < 9; m++)
            bm[m] = make_float2(__shfl_sync(FULLMASK, bv, m),
                                __shfl_sync(FULLMASK, bv, 9 + m));

        // --- bA[t] = sum_m bm[m]*A[m][j0+t]  (m-outer, vector row loads)
        float2 bA[10];
        #pragma unroll
        for (int t = 0; t < 10; t++) bA[t] = make_float2(0.f, 0.f);
        #pragma unroll
        for (int m = 0; m < 9; m++) {
            const float4* rA = reinterpret_cast<const float4*>(sA + m * TBL12 + base12);
            float4 q0 = rA[0], q1 = rA[1], q2 = rA[2];
            float av[10] = {q0.x,q0.y,q0.z,q0.w,q1.x,q1.y,q1.z,q1.w,q2.x,q2.y};
            #pragma unroll
            for (int t = 0; t < 10; t++)
                bA[t] = f2fma(bm[m], dup(av[t]), bA[t]);
        }

        float2 x[10], eta[10], tau[10];
        #pragma unroll
        for (int t = 0; t < 10; t++) {
            x[t] = make_float2(1.f, 1.f);
            eta[t] = make_float2(0.f, 0.f);
            tau[t] = make_float2(0.f, 0.f);
        }

        #pragma unroll 1
        for (int l = 0; l < NLAYERS; l++) {
            const float* sc = sscal + l * 8;
            float gs = sc[0], als = sc[1], lamg = sc[2], invgs = sc[3], invals = sc[4];
            float2 g2 = dup(gs), al2 = dup(als), invg2 = dup(invgs), inval2 = dup(invals);
            const float2* ctab = sct2 + l * 24;
            const float* sHl = sHn + l * (NM * TBL12);

            // --- residual r = bA + al*w - tau + g*u - eta
            float2 xm1 = shfl2(x[9], lm1);
            float2 r[10];
            #pragma unroll
            for (int t = 0; t < 10; t++) {
                float2 xp = (t == 0) ? xm1 : x[t - 1];
                float2 v = f2fma(neg1, x[t], xp);
                v = f2fma(eta[t], invg2, v);
                float2 u; u.x = softt(v.x, lamg); u.y = softt(v.y, lamg);
                float2 w = f2fma(tau[t], inval2, x[t]);
                w.x = fmaxf(w.x, 0.f); w.y = fmaxf(w.y, 0.f);
                float2 s = f2fma(neg1, tau[t], bA[t]);
                s = f2fma(al2, w, s);
                s = f2fma(g2, u, s);
                r[t] = f2fma(neg1, eta[t], s);
            }

            // --- y = C^-1 r : 21-tap circulant conv
            float2 y[10];
            float2 wchunk[10];
            #pragma unroll
            for (int k = 0; k < 10; k++) wchunk[k] = shfl2(r[k], lm1);
            {
                float2 c0 = ctab[0];
                #pragma unroll
                for (int t = 0; t < 10; t++) y[t] = f2mul(c0, wchunk[t]);
            }
            #pragma unroll
            for (int d = 1; d < 10; d++) {
                float2 cd = ctab[d];
                #pragma unroll
                for (int t = 0; t < 10; t++)
                    if (t + d < 10) y[t] = f2fma(cd, wchunk[t + d], y[t]);
            }
            #pragma unroll
            for (int i = 1; i < 20; i++) {
                float2 ci = ctab[i];
                #pragma unroll
                for (int t = 0; t < 10; t++) {
                    int k = t + i - 10;
                    if (k >= 0 && k < 10) y[t] = f2fma(ci, r[k], y[t]);
                }
            }
            #pragma unroll
            for (int k = 0; k < 10; k++) wchunk[k] = shfl2(r[k], lp1);
            #pragma unroll
            for (int i = 11; i < 21; i++) {
                float2 ci = ctab[i];
                #pragma unroll
                for (int t = 0; t < 10; t++) {
                    int k = t + i - 20;
                    if (k >= 0 && k < 10) y[t] = f2fma(ci, wchunk[k], y[t]);
                }
            }

            // --- pd[m] = sum_j y_j A[m][j]  (m-outer vector loads + butterfly)
            float2 pd[9];
            #pragma unroll
            for (int m = 0; m < 9; m++) {
                const float4* rA = reinterpret_cast<const float4*>(sA + m * TBL12 + base12);
                float4 q0 = rA[0], q1 = rA[1], q2 = rA[2];
                float av[10] = {q0.x,q0.y,q0.z,q0.w,q1.x,q1.y,q1.z,q1.w,q2.x,q2.y};
                float2 acc = f2mul(y[0], dup(av[0]));
                #pragma unroll
                for (int t = 1; t < 10; t++)
                    acc = f2fma(y[t], dup(av[t]), acc);
                pd[m] = acc;
            }
            #pragma unroll
            for (int m = 0; m < 9; m++) pd[m] = bfly_sum(pd[m]);

            // --- xn = y + sum_m pd[m] * Hn[m][j]  (m-outer vector loads)
            float2 xn[10];
            #pragma unroll
            for (int t = 0; t < 10; t++) xn[t] = y[t];
            #pragma unroll
            for (int m = 0; m < 9; m++) {
                const float4* rH = reinterpret_cast<const float4*>(sHl + m * TBL12 + base12);
                float4 q0 = rH[0], q1 = rH[1], q2 = rH[2];
                float hv[10] = {q0.x,q0.y,q0.z,q0.w,q1.x,q1.y,q1.z,q1.w,q2.x,q2.y};
                #pragma unroll
                for (int t = 0; t < 10; t++)
                    xn[t] = f2fma(pd[m], dup(hv[t]), xn[t]);
            }

            // --- dual updates (recompute u,w from OLD state)
            float2 xnm1 = shfl2(xn[9], lm1);
            float2 xprev_old = xm1;
            #pragma unroll
            for (int t = 0; t < 10; t++) {
                float2 xp = xprev_old;
                xprev_old = x[t];
                float2 xnp = (t == 0) ? xnm1 : xn[t - 1];
                float2 v = f2fma(neg1, x[t], xp);
                v = f2fma(eta[t], invg2, v);
                float2 u; u.x = softt(v.x, lamg); u.y = softt(v.y, lamg);
                float2 w = f2fma(tau[t], inval2, x[t]);
                w.x = fmaxf(w.x, 0.f); w.y = fmaxf(w.y, 0.f);
                float2 d1 = f2fma(neg1, xn[t], xnp);
                d1 = f2fma(neg1, u, d1);
                eta[t] = f2fma(g2, d1, eta[t]);
                float2 d2 = f2fma(neg1, w, xn[t]);
                tau[t] = f2fma(al2, d2, tau[t]);
                x[t] = xn[t];
            }
        }

        // --- store both rows, coalesced float4 via smem staging
        __syncwarp();
        if (lane < 30) {
            #pragma unroll
            for (int t = 0; t < 10; t++) {
                wstage[j0 + t]       = x[t].x;
                wstage[304 + j0 + t] = x[t].y;
            }
        }
        __syncwarp();
        {
            const float4* st4 = reinterpret_cast<const float4*>(wstage);
            float4* out4 = reinterpret_cast<float4*>(out);
            size_t o0 = row0 * (N / 4);
            for (int idx = lane; idx < N / 4; idx += 32) {
                out4[o0 + idx] = st4[idx];
                out4[o0 + N / 4 + idx] = st4[76 + idx];
            }
        }
        __syncwarp();
    }
}

// ---------------------------------------------------------------------------
extern "C" void kernel_launch(void* const* d_in, const int* in_sizes, int n_in,
                              void* d_out, int out_size) {
    const float* b         = (const float*)d_in[0];
    const float* A         = (const float*)d_in[2];
    const float* gamma_tv  = (const float*)d_in[3];
    const float* lambda_tv = (const float*)d_in[4];
    const float* alpha     = (const float*)d_in[5];
    float* out = (float*)d_out;

    pre_A_kernel<<<(NM * TBL12 + 255) / 256, 256>>>(A);
    pre_layer_kernel<<<NLAYERS, 256>>>(A, gamma_tv, lambda_tv, alpha);

    size_t smembytes = (size_t)(NM * TBL12 * (1 + NLAYERS)            // 20736
                                + NLAYERS * 24 * 2 + NLAYERS * 8      // 280
                                + WARPS * 608) * sizeof(float);       // 6080 -> ~106KB
    cudaFuncSetAttribute(ladmm_main,
                         cudaFuncAttributeMaxDynamicSharedMemorySize,
                         (int)smembytes);
    int pairsPerBlock = WARPS * RPW;
    int grid = (NPAIRS + pairsPerBlock - 1) / pairsPerBlock;
    ladmm_main<<<grid, WARPS * 32, smembytes>>>(b, out);
}

// round 12
// speedup vs baseline: 1.3398x; 1.1834x over previous
#include <cuda_runtime.h>
#include <math.h>

#define N       300
#define NM      9
#define BATCH   131072
#define NLAYERS 5
#define KTAP    10
#define TAPS    (2*KTAP + 1)   // 21
#define TBL12   384            // stride-12 table: row m occupies [m*384 + 12L + t]
#define WARPS   8
#define RPW     8              // row-PAIRS per warp
#define NPAIRS  (BATCH / 2)
#define FULLMASK 0xffffffffu

static __device__ double g_cfull[NLAYERS][N];
static __device__ float  g_G[NLAYERS][NM * N];
static __device__ float  g_At[NM * TBL12];           // A[m][j], j=10L+t at [m*384+12L+t]
static __device__ float  g_Hn[NLAYERS][NM * TBL12];  // NEGATED H, same layout
static __device__ float  g_ct[NLAYERS][24];          // conv taps ct[i]=c[|i-10|]
static __device__ float  g_scal[NLAYERS][8];

// ---------------------------------------------------------------------------
// packed f32x2 + warp helpers (sm_103a)
// ---------------------------------------------------------------------------
__device__ __forceinline__ float2 f2fma(float2 a, float2 b, float2 c) {
    unsigned long long ra = reinterpret_cast<unsigned long long&>(a);
    unsigned long long rb = reinterpret_cast<unsigned long long&>(b);
    unsigned long long rc = reinterpret_cast<unsigned long long&>(c);
    unsigned long long rd;
    asm("fma.rn.f32x2 %0, %1, %2, %3;" : "=l"(rd) : "l"(ra), "l"(rb), "l"(rc));
    return reinterpret_cast<float2&>(rd);
}
__device__ __forceinline__ float2 f2add(float2 a, float2 b) {
    unsigned long long ra = reinterpret_cast<unsigned long long&>(a);
    unsigned long long rb = reinterpret_cast<unsigned long long&>(b);
    unsigned long long rd;
    asm("add.rn.f32x2 %0, %1, %2;" : "=l"(rd) : "l"(ra), "l"(rb));
    return reinterpret_cast<float2&>(rd);
}
__device__ __forceinline__ float2 f2mul(float2 a, float2 b) {
    unsigned long long ra = reinterpret_cast<unsigned long long&>(a);
    unsigned long long rb = reinterpret_cast<unsigned long long&>(b);
    unsigned long long rd;
    asm("mul.rn.f32x2 %0, %1, %2;" : "=l"(rd) : "l"(ra), "l"(rb));
    return reinterpret_cast<float2&>(rd);
}
__device__ __forceinline__ float2 dup(float s) { return make_float2(s, s); }
__device__ __forceinline__ float2 shfl2(float2 v, int src) {
    float2 r;
    r.x = __shfl_sync(FULLMASK, v.x, src);
    r.y = __shfl_sync(FULLMASK, v.y, src);
    return r;
}
__device__ __forceinline__ float2 bfly_sum(float2 v) {
    #pragma unroll
    for (int off = 16; off >= 1; off >>= 1) {
        float sx = __shfl_xor_sync(FULLMASK, v.x, off);
        float sy = __shfl_xor_sync(FULLMASK, v.y, off);
        v = f2add(v, make_float2(sx, sy));
    }
    return v;
}
__device__ __forceinline__ float softt(float v, float lam) {
    return copysignf(fmaxf(fabsf(v) - lam, 0.f), v);
}

// ---------------------------------------------------------------------------
__global__ void pre_A_kernel(const float* __restrict__ A) {
    int idx = blockIdx.x * blockDim.x + threadIdx.x;
    if (idx < NM * TBL12) {
        int m = idx / TBL12, ii = idx % TBL12;
        int L = ii / 12, t = ii % 12;
        int j = L * 10 + t;
        g_At[idx] = (t < 10 && j < N) ? A[m * N + j] : 0.0f;
    }
}

// ---------------------------------------------------------------------------
__global__ void pre_layer_kernel(const float* __restrict__ A,
                                 const float* __restrict__ gamma_tv,
                                 const float* __restrict__ lambda_tv,
                                 const float* __restrict__ alpha) {
    const double PI = 3.14159265358979323846;
    int l = blockIdx.x;
    int tid = threadIdx.x;
    double g = (double)gamma_tv[l], al = (double)alpha[l];

    __shared__ double costab[N];
    __shared__ double invlam[N];
    for (int m = tid; m < N; m += blockDim.x) {
        double th = 2.0 * PI * (double)m / (double)N;
        costab[m] = cos(th);
        invlam[m] = 1.0 / (al + 2.0 * g - 2.0 * g * costab[m]);
    }
    __syncthreads();

    for (int k = tid; k < N; k += blockDim.x) {
        double s = 0.0;
        int mk = 0;
        for (int m = 0; m < N; m++) {
            s += costab[mk] * invlam[m];
            mk += k; if (mk >= N) mk -= N;
        }
        g_cfull[l][k] = s / (double)N;
    }
    __syncthreads();

    for (int idx = tid; idx < NM * N; idx += blockDim.x) {
        int m = idx / N, j = idx % N;
        float s = 0.f;
        for (int t = 0; t < N; t++) {
            int d = j - t; if (d < 0) d += N;
            s += A[m * N + t] * (float)g_cfull[l][d];
        }
        g_G[l][m * N + j] = s;
    }
    __syncthreads();

    __shared__ double S9[81], S9i[81];
    for (int idx = tid; idx < 81; idx += blockDim.x) {
        int p = idx / 9, q = idx % 9;
        double s = (p == q) ? 1.0 : 0.0;
        for (int j = 0; j < N; j++)
            s += (double)g_G[l][p * N + j] * (double)A[q * N + j];
        S9[idx] = s;
    }
    __syncthreads();

    if (tid == 0) {
        for (int i = 0; i < 81; i++) S9i[i] = ((i / 9) == (i % 9)) ? 1.0 : 0.0;
        for (int col = 0; col < 9; col++) {
            int piv = col; double best = fabs(S9[col * 9 + col]);
            for (int rr = col + 1; rr < 9; rr++) {
                double v = fabs(S9[rr * 9 + col]);
                if (v > best) { best = v; piv = rr; }
            }
            if (piv != col) {
                for (int c2 = 0; c2 < 9; c2++) {
                    double tmp = S9[col * 9 + c2]; S9[col * 9 + c2] = S9[piv * 9 + c2]; S9[piv * 9 + c2] = tmp;
                    tmp = S9i[col * 9 + c2]; S9i[col * 9 + c2] = S9i[piv * 9 + c2]; S9i[piv * 9 + c2] = tmp;
                }
            }
            double d = 1.0 / S9[col * 9 + col];
            for (int c2 = 0; c2 < 9; c2++) { S9[col * 9 + c2] *= d; S9i[col * 9 + c2] *= d; }
            for (int rr = 0; rr < 9; rr++) {
                if (rr == col) continue;
                double f = S9[rr * 9 + col];
                for (int c2 = 0; c2 < 9; c2++) {
                    S9[rr * 9 + c2]  -= f * S9[col * 9 + c2];
                    S9i[rr * 9 + c2] -= f * S9i[col * 9 + c2];
                }
            }
        }
    }
    __syncthreads();

    for (int idx = tid; idx < NM * TBL12; idx += blockDim.x) {
        int m = idx / TBL12, ii = idx % TBL12;
        int L = ii / 12, t = ii % 12;
        int j = L * 10 + t;
        float s = 0.f;
        if (t < 10 && j < N) {
            for (int q = 0; q < NM; q++)
                s -= (float)S9i[m * 9 + q] * g_G[l][q * N + j];
        }
        g_Hn[l][idx] = s;
    }
    for (int i = tid; i < 24; i += blockDim.x) {
        float v = 0.f;
        if (i < TAPS) { int d = i - KTAP; if (d < 0) d = -d; v = (float)g_cfull[l][d]; }
        g_ct[l][i] = v;
    }
    if (tid == 0) {
        g_scal[l][0] = (float)g;
        g_scal[l][1] = (float)al;
        g_scal[l][2] = (float)((double)lambda_tv[l] / g);
        g_scal[l][3] = (float)(1.0 / g);
        g_scal[l][4] = (float)(1.0 / al);
    }
}

// ---------------------------------------------------------------------------
// Main fused kernel: R7 structure (8 warps, state in registers, 1 block/SM)
// + u/w cached across each layer (removes their recompute in the dual phase;
// dual op sequence bitwise-identical to R7).
// Lane L (0..29) owns elements j = 10L..10L+9.
// ---------------------------------------------------------------------------
__global__ void __launch_bounds__(WARPS * 32)
ladmm_main(const float* __restrict__ b, float* __restrict__ out) {
    extern __shared__ float sm[];
    float*  sA    = sm;                                   // NM*TBL12      = 3456
    float*  sHn   = sA + NM * TBL12;                      // 5*NM*TBL12    = 17280
    float2* sct2  = (float2*)(sHn + NLAYERS * NM * TBL12);// 5*24 float2
    float*  sscal = (float*)(sct2 + NLAYERS * 24);        // 40
    float*  stage = sscal + 40;                           // WARPS*608

    int tid = threadIdx.x;
    for (int i = tid; i < NM * TBL12; i += WARPS * 32) sA[i] = g_At[i];
    for (int i = tid; i < NLAYERS * NM * TBL12; i += WARPS * 32) sHn[i] = (&g_Hn[0][0])[i];
    for (int i = tid; i < NLAYERS * 24; i += WARPS * 32) {
        float v = (&g_ct[0][0])[i];
        sct2[i] = make_float2(v, v);
    }
    for (int i = tid; i < NLAYERS * 8; i += WARPS * 32) sscal[i] = (&g_scal[0][0])[i];
    __syncthreads();

    int wid = tid >> 5, lane = tid & 31;
    int base12 = lane * 12;
    int j0 = lane * 10;
    int lm1 = (lane + 29) % 30;
    int lp1 = (lane + 1) % 30;

    const float2 neg1 = make_float2(-1.f, -1.f);
    float* wstage = stage + wid * 608;

    #pragma unroll 1
    for (int rit = 0; rit < RPW; rit++) {
        int pairIdx = blockIdx.x * (WARPS * RPW) + wid * RPW + rit;
        size_t row0 = (size_t)pairIdx * 2;

        // --- b rows -> bm[m] packed pairs
        float bv = (lane < 2 * NM) ? b[(size_t)pairIdx * (2 * NM) + lane] : 0.f;
        float2 bm[9];
        #pragma unroll
        for (int m = 0; m < 9; m++)
            bm[m] = make_float2(__shfl_sync(FULLMASK, bv, m),
                                __shfl_sync(FULLMASK, bv, 9 + m));

        // --- bA[t] = sum_m bm[m]*A[m][j0+t]  (m-outer, vector row loads)
        float2 bA[10];
        #pragma unroll
        for (int t = 0; t < 10; t++) bA[t] = make_float2(0.f, 0.f);
        #pragma unroll
        for (int m = 0; m < 9; m++) {
            const float4* rA = reinterpret_cast<const float4*>(sA + m * TBL12 + base12);
            float4 q0 = rA[0], q1 = rA[1], q2 = rA[2];
            float av[10] = {q0.x,q0.y,q0.z,q0.w,q1.x,q1.y,q1.z,q1.w,q2.x,q2.y};
            #pragma unroll
            for (int t = 0; t < 10; t++)
                bA[t] = f2fma(bm[m], dup(av[t]), bA[t]);
        }

        float2 x[10], eta[10], tau[10];
        #pragma unroll
        for (int t = 0; t < 10; t++) {
            x[t] = make_float2(1.f, 1.f);
            eta[t] = make_float2(0.f, 0.f);
            tau[t] = make_float2(0.f, 0.f);
        }

        #pragma unroll 1
        for (int l = 0; l < NLAYERS; l++) {
            const float* sc = sscal + l * 8;
            float gs = sc[0], als = sc[1], lamg = sc[2], invgs = sc[3], invals = sc[4];
            float2 g2 = dup(gs), al2 = dup(als), invg2 = dup(invgs), inval2 = dup(invals);
            const float2* ctab = sct2 + l * 24;
            const float* sHl = sHn + l * (NM * TBL12);

            // --- residual r = bA + al*w - tau + g*u - eta   (u,w kept live)
            float2 xm1 = shfl2(x[9], lm1);
            float2 r[10], uu[10], ww[10];
            #pragma unroll
            for (int t = 0; t < 10; t++) {
                float2 xp = (t == 0) ? xm1 : x[t - 1];
                float2 v = f2fma(neg1, x[t], xp);
                v = f2fma(eta[t], invg2, v);
                float2 u; u.x = softt(v.x, lamg); u.y = softt(v.y, lamg);
                float2 w = f2fma(tau[t], inval2, x[t]);
                w.x = fmaxf(w.x, 0.f); w.y = fmaxf(w.y, 0.f);
                uu[t] = u; ww[t] = w;
                float2 s = f2fma(neg1, tau[t], bA[t]);
                s = f2fma(al2, w, s);
                s = f2fma(g2, u, s);
                r[t] = f2fma(neg1, eta[t], s);
            }

            // --- y = C^-1 r : 21-tap circulant conv
            float2 y[10];
            float2 wchunk[10];
            #pragma unroll
            for (int k = 0; k < 10; k++) wchunk[k] = shfl2(r[k], lm1);
            {
                float2 c0 = ctab[0];
                #pragma unroll
                for (int t = 0; t < 10; t++) y[t] = f2mul(c0, wchunk[t]);
            }
            #pragma unroll
            for (int d = 1; d < 10; d++) {
                float2 cd = ctab[d];
                #pragma unroll
                for (int t = 0; t < 10; t++)
                    if (t + d < 10) y[t] = f2fma(cd, wchunk[t + d], y[t]);
            }
            #pragma unroll
            for (int i = 1; i < 20; i++) {
                float2 ci = ctab[i];
                #pragma unroll
                for (int t = 0; t < 10; t++) {
                    int k = t + i - 10;
                    if (k >= 0 && k < 10) y[t] = f2fma(ci, r[k], y[t]);
                }
            }
            #pragma unroll
            for (int k = 0; k < 10; k++) wchunk[k] = shfl2(r[k], lp1);
            #pragma unroll
            for (int i = 11; i < 21; i++) {
                float2 ci = ctab[i];
                #pragma unroll
                for (int t = 0; t < 10; t++) {
                    int k = t + i - 20;
                    if (k >= 0 && k < 10) y[t] = f2fma(ci, wchunk[k], y[t]);
                }
            }

            // --- pd[m] = sum_j y_j A[m][j]  (m-outer vector loads + butterfly)
            float2 pd[9];
            #pragma unroll
            for (int m = 0; m < 9; m++) {
                const float4* rA = reinterpret_cast<const float4*>(sA + m * TBL12 + base12);
                float4 q0 = rA[0], q1 = rA[1], q2 = rA[2];
                float av[10] = {q0.x,q0.y,q0.z,q0.w,q1.x,q1.y,q1.z,q1.w,q2.x,q2.y};
                float2 acc = f2mul(y[0], dup(av[0]));
                #pragma unroll
                for (int t = 1; t < 10; t++)
                    acc = f2fma(y[t], dup(av[t]), acc);
                pd[m] = acc;
            }
            #pragma unroll
            for (int m = 0; m < 9; m++) pd[m] = bfly_sum(pd[m]);

            // --- xn = y + sum_m pd[m] * Hn[m][j]  (m-outer vector loads)
            float2 xn[10];
            #pragma unroll
            for (int t = 0; t < 10; t++) xn[t] = y[t];
            #pragma unroll
            for (int m = 0; m < 9; m++) {
                const float4* rH = reinterpret_cast<const float4*>(sHl + m * TBL12 + base12);
                float4 q0 = rH[0], q1 = rH[1], q2 = rH[2];
                float hv[10] = {q0.x,q0.y,q0.z,q0.w,q1.x,q1.y,q1.z,q1.w,q2.x,q2.y};
                #pragma unroll
                for (int t = 0; t < 10; t++)
                    xn[t] = f2fma(pd[m], dup(hv[t]), xn[t]);
            }

            // --- dual updates (u,w reused from residual phase; op sequence
            //     bitwise-identical to the recompute version)
            float2 xnm1 = shfl2(xn[9], lm1);
            #pragma unroll
            for (int t = 0; t < 10; t++) {
                float2 xnp = (t == 0) ? xnm1 : xn[t - 1];
                float2 d1 = f2fma(neg1, xn[t], xnp);
                d1 = f2fma(neg1, uu[t], d1);
                eta[t] = f2fma(g2, d1, eta[t]);
                float2 d2 = f2fma(neg1, ww[t], xn[t]);
                tau[t] = f2fma(al2, d2, tau[t]);
                x[t] = xn[t];
            }
        }

        // --- store both rows, coalesced float4 via smem staging
        __syncwarp();
        if (lane < 30) {
            #pragma unroll
            for (int t = 0; t < 10; t++) {
                wstage[j0 + t]       = x[t].x;
                wstage[304 + j0 + t] = x[t].y;
            }
        }
        __syncwarp();
        {
            const float4* st4 = reinterpret_cast<const float4*>(wstage);
            float4* out4 = reinterpret_cast<float4*>(out);
            size_t o0 = row0 * (N / 4);
            for (int idx = lane; idx < N / 4; idx += 32) {
                out4[o0 + idx] = st4[idx];
                out4[o0 + N / 4 + idx] = st4[76 + idx];
            }
        }
        __syncwarp();
    }
}

// ---------------------------------------------------------------------------
extern "C" void kernel_launch(void* const* d_in, const int* in_sizes, int n_in,
                              void* d_out, int out_size) {
    const float* b         = (const float*)d_in[0];
    const float* A         = (const float*)d_in[2];
    const float* gamma_tv  = (const float*)d_in[3];
    const float* lambda_tv = (const float*)d_in[4];
    const float* alpha     = (const float*)d_in[5];
    float* out = (float*)d_out;

    pre_A_kernel<<<(NM * TBL12 + 255) / 256, 256>>>(A);
    pre_layer_kernel<<<NLAYERS, 256>>>(A, gamma_tv, lambda_tv, alpha);

    size_t smembytes = (size_t)(NM * TBL12 * (1 + NLAYERS)            // 20736
                                + NLAYERS * 24 * 2 + NLAYERS * 8      // 280
                                + WARPS * 608) * sizeof(float);       // 4864 -> ~103KB
    cudaFuncSetAttribute(ladmm_main,
                         cudaFuncAttributeMaxDynamicSharedMemorySize,
                         (int)smembytes);
    int grid = NPAIRS / (WARPS * RPW);
    ladmm_main<<<grid, WARPS * 32, smembytes>>>(b, out);
}

// round 13
// speedup vs baseline: 1.3421x; 1.0018x over previous
#include <cuda_runtime.h>
#include <math.h>

#define N       300
#define NM      9
#define BATCH   131072
#define NLAYERS 5
#define KTAP    10
#define TAPS    (2*KTAP + 1)   // 21
#define TBL12   384            // stride-12 table: row m occupies [m*384 + 12L + t]
#define WARPS   8
#define RPW     8              // row-PAIRS per warp
#define NPAIRS  (BATCH / 2)
#define FULLMASK 0xffffffffu

static __device__ double g_cfull[NLAYERS][N];
static __device__ float  g_G[NLAYERS][NM * N];
static __device__ float  g_At[NM * TBL12];           // A[m][j], j=10L+t at [m*384+12L+t]
static __device__ float  g_Hn[NLAYERS][NM * TBL12];  // NEGATED H, same layout
static __device__ float  g_ct[NLAYERS][24];          // conv taps ct[i]=c[|i-10|]
static __device__ float  g_scal[NLAYERS][8];

// ---------------------------------------------------------------------------
// packed f32x2 + warp helpers (sm_103a)
// ---------------------------------------------------------------------------
__device__ __forceinline__ float2 f2fma(float2 a, float2 b, float2 c) {
    unsigned long long ra = reinterpret_cast<unsigned long long&>(a);
    unsigned long long rb = reinterpret_cast<unsigned long long&>(b);
    unsigned long long rc = reinterpret_cast<unsigned long long&>(c);
    unsigned long long rd;
    asm("fma.rn.f32x2 %0, %1, %2, %3;" : "=l"(rd) : "l"(ra), "l"(rb), "l"(rc));
    return reinterpret_cast<float2&>(rd);
}
__device__ __forceinline__ float2 f2add(float2 a, float2 b) {
    unsigned long long ra = reinterpret_cast<unsigned long long&>(a);
    unsigned long long rb = reinterpret_cast<unsigned long long&>(b);
    unsigned long long rd;
    asm("add.rn.f32x2 %0, %1, %2;" : "=l"(rd) : "l"(ra), "l"(rb));
    return reinterpret_cast<float2&>(rd);
}
__device__ __forceinline__ float2 f2mul(float2 a, float2 b) {
    unsigned long long ra = reinterpret_cast<unsigned long long&>(a);
    unsigned long long rb = reinterpret_cast<unsigned long long&>(b);
    unsigned long long rd;
    asm("mul.rn.f32x2 %0, %1, %2;" : "=l"(rd) : "l"(ra), "l"(rb));
    return reinterpret_cast<float2&>(rd);
}
__device__ __forceinline__ float2 dup(float s) { return make_float2(s, s); }
__device__ __forceinline__ float2 shfl2(float2 v, int src) {
    float2 r;
    r.x = __shfl_sync(FULLMASK, v.x, src);
    r.y = __shfl_sync(FULLMASK, v.y, src);
    return r;
}
__device__ __forceinline__ float2 bfly_sum(float2 v) {
    #pragma unroll
    for (int off = 16; off >= 1; off >>= 1) {
        float sx = __shfl_xor_sync(FULLMASK, v.x, off);
        float sy = __shfl_xor_sync(FULLMASK, v.y, off);
        v = f2add(v, make_float2(sx, sy));
    }
    return v;
}
__device__ __forceinline__ float softt(float v, float lam) {
    return copysignf(fmaxf(fabsf(v) - lam, 0.f), v);
}

// ---------------------------------------------------------------------------
// Merged precompute: blocks 0..NLAYERS-1 do per-layer tables; block NLAYERS
// fills the A table. ONE launch per kernel_launch call so the ncu capture
// (-s 5 -c 1) lands on the MAIN kernel (launch sequence pre,main,pre,main,..).
// ---------------------------------------------------------------------------
__global__ void pre_all_kernel(const float* __restrict__ A,
                               const float* __restrict__ gamma_tv,
                               const float* __restrict__ lambda_tv,
                               const float* __restrict__ alpha) {
    int tid = threadIdx.x;

    if (blockIdx.x == NLAYERS) {
        // A table fill
        for (int idx = tid; idx < NM * TBL12; idx += blockDim.x) {
            int m = idx / TBL12, ii = idx % TBL12;
            int L = ii / 12, t = ii % 12;
            int j = L * 10 + t;
            g_At[idx] = (t < 10 && j < N) ? A[m * N + j] : 0.0f;
        }
        return;
    }

    const double PI = 3.14159265358979323846;
    int l = blockIdx.x;
    double g = (double)gamma_tv[l], al = (double)alpha[l];

    __shared__ double costab[N];
    __shared__ double invlam[N];
    for (int m = tid; m < N; m += blockDim.x) {
        double th = 2.0 * PI * (double)m / (double)N;
        costab[m] = cos(th);
        invlam[m] = 1.0 / (al + 2.0 * g - 2.0 * g * costab[m]);
    }
    __syncthreads();

    for (int k = tid; k < N; k += blockDim.x) {
        double s = 0.0;
        int mk = 0;
        for (int m = 0; m < N; m++) {
            s += costab[mk] * invlam[m];
            mk += k; if (mk >= N) mk -= N;
        }
        g_cfull[l][k] = s / (double)N;
    }
    __syncthreads();

    for (int idx = tid; idx < NM * N; idx += blockDim.x) {
        int m = idx / N, j = idx % N;
        float s = 0.f;
        for (int t = 0; t < N; t++) {
            int d = j - t; if (d < 0) d += N;
            s += A[m * N + t] * (float)g_cfull[l][d];
        }
        g_G[l][m * N + j] = s;
    }
    __syncthreads();

    __shared__ double S9[81], S9i[81];
    for (int idx = tid; idx < 81; idx += blockDim.x) {
        int p = idx / 9, q = idx % 9;
        double s = (p == q) ? 1.0 : 0.0;
        for (int j = 0; j < N; j++)
            s += (double)g_G[l][p * N + j] * (double)A[q * N + j];
        S9[idx] = s;
    }
    __syncthreads();

    if (tid == 0) {
        for (int i = 0; i < 81; i++) S9i[i] = ((i / 9) == (i % 9)) ? 1.0 : 0.0;
        for (int col = 0; col < 9; col++) {
            int piv = col; double best = fabs(S9[col * 9 + col]);
            for (int rr = col + 1; rr < 9; rr++) {
                double v = fabs(S9[rr * 9 + col]);
                if (v > best) { best = v; piv = rr; }
            }
            if (piv != col) {
                for (int c2 = 0; c2 < 9; c2++) {
                    double tmp = S9[col * 9 + c2]; S9[col * 9 + c2] = S9[piv * 9 + c2]; S9[piv * 9 + c2] = tmp;
                    tmp = S9i[col * 9 + c2]; S9i[col * 9 + c2] = S9i[piv * 9 + c2]; S9i[piv * 9 + c2] = tmp;
                }
            }
            double d = 1.0 / S9[col * 9 + col];
            for (int c2 = 0; c2 < 9; c2++) { S9[col * 9 + c2] *= d; S9i[col * 9 + c2] *= d; }
            for (int rr = 0; rr < 9; rr++) {
                if (rr == col) continue;
                double f = S9[rr * 9 + col];
                for (int c2 = 0; c2 < 9; c2++) {
                    S9[rr * 9 + c2]  -= f * S9[col * 9 + c2];
                    S9i[rr * 9 + c2] -= f * S9i[col * 9 + c2];
                }
            }
        }
    }
    __syncthreads();

    for (int idx = tid; idx < NM * TBL12; idx += blockDim.x) {
        int m = idx / TBL12, ii = idx % TBL12;
        int L = ii / 12, t = ii % 12;
        int j = L * 10 + t;
        float s = 0.f;
        if (t < 10 && j < N) {
            for (int q = 0; q < NM; q++)
                s -= (float)S9i[m * 9 + q] * g_G[l][q * N + j];
        }
        g_Hn[l][idx] = s;
    }
    for (int i = tid; i < 24; i += blockDim.x) {
        float v = 0.f;
        if (i < TAPS) { int d = i - KTAP; if (d < 0) d = -d; v = (float)g_cfull[l][d]; }
        g_ct[l][i] = v;
    }
    if (tid == 0) {
        g_scal[l][0] = (float)g;
        g_scal[l][1] = (float)al;
        g_scal[l][2] = (float)((double)lambda_tv[l] / g);
        g_scal[l][3] = (float)(1.0 / g);
        g_scal[l][4] = (float)(1.0 / al);
    }
}

// ---------------------------------------------------------------------------
// Main fused kernel: identical to R12 (897us). 8 warps, state in registers,
// 1 block/SM, u/w cached across each layer.
// Lane L (0..29) owns elements j = 10L..10L+9.
// ---------------------------------------------------------------------------
__global__ void __launch_bounds__(WARPS * 32)
ladmm_main(const float* __restrict__ b, float* __restrict__ out) {
    extern __shared__ float sm[];
    float*  sA    = sm;                                   // NM*TBL12      = 3456
    float*  sHn   = sA + NM * TBL12;                      // 5*NM*TBL12    = 17280
    float2* sct2  = (float2*)(sHn + NLAYERS * NM * TBL12);// 5*24 float2
    float*  sscal = (float*)(sct2 + NLAYERS * 24);        // 40
    float*  stage = sscal + 40;                           // WARPS*608

    int tid = threadIdx.x;
    for (int i = tid; i < NM * TBL12; i += WARPS * 32) sA[i] = g_At[i];
    for (int i = tid; i < NLAYERS * NM * TBL12; i += WARPS * 32) sHn[i] = (&g_Hn[0][0])[i];
    for (int i = tid; i < NLAYERS * 24; i += WARPS * 32) {
        float v = (&g_ct[0][0])[i];
        sct2[i] = make_float2(v, v);
    }
    for (int i = tid; i < NLAYERS * 8; i += WARPS * 32) sscal[i] = (&g_scal[0][0])[i];
    __syncthreads();

    int wid = tid >> 5, lane = tid & 31;
    int base12 = lane * 12;
    int j0 = lane * 10;
    int lm1 = (lane + 29) % 30;
    int lp1 = (lane + 1) % 30;

    const float2 neg1 = make_float2(-1.f, -1.f);
    float* wstage = stage + wid * 608;

    #pragma unroll 1
    for (int rit = 0; rit < RPW; rit++) {
        int pairIdx = blockIdx.x * (WARPS * RPW) + wid * RPW + rit;
        size_t row0 = (size_t)pairIdx * 2;

        // --- b rows -> bm[m] packed pairs
        float bv = (lane < 2 * NM) ? b[(size_t)pairIdx * (2 * NM) + lane] : 0.f;
        float2 bm[9];
        #pragma unroll
        for (int m = 0; m < 9; m++)
            bm[m] = make_float2(__shfl_sync(FULLMASK, bv, m),
                                __shfl_sync(FULLMASK, bv, 9 + m));

        // --- bA[t] = sum_m bm[m]*A[m][j0+t]  (m-outer, vector row loads)
        float2 bA[10];
        #pragma unroll
        for (int t = 0; t < 10; t++) bA[t] = make_float2(0.f, 0.f);
        #pragma unroll
        for (int m = 0; m < 9; m++) {
            const float4* rA = reinterpret_cast<const float4*>(sA + m * TBL12 + base12);
            float4 q0 = rA[0], q1 = rA[1], q2 = rA[2];
            float av[10] = {q0.x,q0.y,q0.z,q0.w,q1.x,q1.y,q1.z,q1.w,q2.x,q2.y};
            #pragma unroll
            for (int t = 0; t < 10; t++)
                bA[t] = f2fma(bm[m], dup(av[t]), bA[t]);
        }

        float2 x[10], eta[10], tau[10];
        #pragma unroll
        for (int t = 0; t < 10; t++) {
            x[t] = make_float2(1.f, 1.f);
            eta[t] = make_float2(0.f, 0.f);
            tau[t] = make_float2(0.f, 0.f);
        }

        #pragma unroll 1
        for (int l = 0; l < NLAYERS; l++) {
            const float* sc = sscal + l * 8;
            float gs = sc[0], als = sc[1], lamg = sc[2], invgs = sc[3], invals = sc[4];
            float2 g2 = dup(gs), al2 = dup(als), invg2 = dup(invgs), inval2 = dup(invals);
            const float2* ctab = sct2 + l * 24;
            const float* sHl = sHn + l * (NM * TBL12);

            // --- residual r = bA + al*w - tau + g*u - eta   (u,w kept live)
            float2 xm1 = shfl2(x[9], lm1);
            float2 r[10], uu[10], ww[10];
            #pragma unroll
            for (int t = 0; t < 10; t++) {
                float2 xp = (t == 0) ? xm1 : x[t - 1];
                float2 v = f2fma(neg1, x[t], xp);
                v = f2fma(eta[t], invg2, v);
                float2 u; u.x = softt(v.x, lamg); u.y = softt(v.y, lamg);
                float2 w = f2fma(tau[t], inval2, x[t]);
                w.x = fmaxf(w.x, 0.f); w.y = fmaxf(w.y, 0.f);
                uu[t] = u; ww[t] = w;
                float2 s = f2fma(neg1, tau[t], bA[t]);
                s = f2fma(al2, w, s);
                s = f2fma(g2, u, s);
                r[t] = f2fma(neg1, eta[t], s);
            }

            // --- y = C^-1 r : 21-tap circulant conv
            float2 y[10];
            float2 wchunk[10];
            #pragma unroll
            for (int k = 0; k < 10; k++) wchunk[k] = shfl2(r[k], lm1);
            {
                float2 c0 = ctab[0];
                #pragma unroll
                for (int t = 0; t < 10; t++) y[t] = f2mul(c0, wchunk[t]);
            }
            #pragma unroll
            for (int d = 1; d < 10; d++) {
                float2 cd = ctab[d];
                #pragma unroll
                for (int t = 0; t < 10; t++)
                    if (t + d < 10) y[t] = f2fma(cd, wchunk[t + d], y[t]);
            }
            #pragma unroll
            for (int i = 1; i < 20; i++) {
                float2 ci = ctab[i];
                #pragma unroll
                for (int t = 0; t < 10; t++) {
                    int k = t + i - 10;
                    if (k >= 0 && k < 10) y[t] = f2fma(ci, r[k], y[t]);
                }
            }
            #pragma unroll
            for (int k = 0; k < 10; k++) wchunk[k] = shfl2(r[k], lp1);
            #pragma unroll
            for (int i = 11; i < 21; i++) {
                float2 ci = ctab[i];
                #pragma unroll
                for (int t = 0; t < 10; t++) {
                    int k = t + i - 20;
                    if (k >= 0 && k < 10) y[t] = f2fma(ci, wchunk[k], y[t]);
                }
            }

            // --- pd[m] = sum_j y_j A[m][j]  (m-outer vector loads + butterfly)
            float2 pd[9];
            #pragma unroll
            for (int m = 0; m < 9; m++) {
                const float4* rA = reinterpret_cast<const float4*>(sA + m * TBL12 + base12);
                float4 q0 = rA[0], q1 = rA[1], q2 = rA[2];
                float av[10] = {q0.x,q0.y,q0.z,q0.w,q1.x,q1.y,q1.z,q1.w,q2.x,q2.y};
                float2 acc = f2mul(y[0], dup(av[0]));
                #pragma unroll
                for (int t = 1; t < 10; t++)
                    acc = f2fma(y[t], dup(av[t]), acc);
                pd[m] = acc;
            }
            #pragma unroll
            for (int m = 0; m < 9; m++) pd[m] = bfly_sum(pd[m]);

            // --- xn = y + sum_m pd[m] * Hn[m][j]  (m-outer vector loads)
            float2 xn[10];
            #pragma unroll
            for (int t = 0; t < 10; t++) xn[t] = y[t];
            #pragma unroll
            for (int m = 0; m < 9; m++) {
                const float4* rH = reinterpret_cast<const float4*>(sHl + m * TBL12 + base12);
                float4 q0 = rH[0], q1 = rH[1], q2 = rH[2];
                float hv[10] = {q0.x,q0.y,q0.z,q0.w,q1.x,q1.y,q1.z,q1.w,q2.x,q2.y};
                #pragma unroll
                for (int t = 0; t < 10; t++)
                    xn[t] = f2fma(pd[m], dup(hv[t]), xn[t]);
            }

            // --- dual updates (u,w reused from residual phase)
            float2 xnm1 = shfl2(xn[9], lm1);
            #pragma unroll
            for (int t = 0; t < 10; t++) {
                float2 xnp = (t == 0) ? xnm1 : xn[t - 1];
                float2 d1 = f2fma(neg1, xn[t], xnp);
                d1 = f2fma(neg1, uu[t], d1);
                eta[t] = f2fma(g2, d1, eta[t]);
                float2 d2 = f2fma(neg1, ww[t], xn[t]);
                tau[t] = f2fma(al2, d2, tau[t]);
                x[t] = xn[t];
            }
        }

        // --- store both rows, coalesced float4 via smem staging
        __syncwarp();
        if (lane < 30) {
            #pragma unroll
            for (int t = 0; t < 10; t++) {
                wstage[j0 + t]       = x[t].x;
                wstage[304 + j0 + t] = x[t].y;
            }
        }
        __syncwarp();
        {
            const float4* st4 = reinterpret_cast<const float4*>(wstage);
            float4* out4 = reinterpret_cast<float4*>(out);
            size_t o0 = row0 * (N / 4);
            for (int idx = lane; idx < N / 4; idx += 32) {
                out4[o0 + idx] = st4[idx];
                out4[o0 + N / 4 + idx] = st4[76 + idx];
            }
        }
        __syncwarp();
    }
}

// ---------------------------------------------------------------------------
extern "C" void kernel_launch(void* const* d_in, const int* in_sizes, int n_in,
                              void* d_out, int out_size) {
    const float* b         = (const float*)d_in[0];
    const float* A         = (const float*)d_in[2];
    const float* gamma_tv  = (const float*)d_in[3];
    const float* lambda_tv = (const float*)d_in[4];
    const float* alpha     = (const float*)d_in[5];
    float* out = (float*)d_out;

    pre_all_kernel<<<NLAYERS + 1, 256>>>(A, gamma_tv, lambda_tv, alpha);

    size_t smembytes = (size_t)(NM * TBL12 * (1 + NLAYERS)            // 20736
                                + NLAYERS * 24 * 2 + NLAYERS * 8      // 280
                                + WARPS * 608) * sizeof(float);       // 4864 -> ~103KB
    cudaFuncSetAttribute(ladmm_main,
                         cudaFuncAttributeMaxDynamicSharedMemorySize,
                         (int)smembytes);
    int grid = NPAIRS / (WARPS * RPW);
    ladmm_main<<<grid, WARPS * 32, smembytes>>>(b, out);
}

// round 14
// speedup vs baseline: 1.7616x; 1.3126x over previous
#include <cuda_runtime.h>
#include <math.h>

#define N       300
#define NM      9
#define BATCH   131072
#define NLAYERS 5
#define KTAP    9
#define TAPS    (2*KTAP + 1)   // 19
#define TBL12   384            // stride-12 table: row m occupies [m*384 + 12L + t]
#define WARPS   8
#define RPW     8              // row-PAIRS per warp
#define NPAIRS  (BATCH / 2)
#define FULLMASK 0xffffffffu

static __device__ double g_cfull[NLAYERS][N];
static __device__ float  g_G[NLAYERS][NM * N];
static __device__ float  g_At[NM * TBL12];           // A[m][j], j=10L+t at [m*384+12L+t]
static __device__ float  g_Hn[NLAYERS][NM * TBL12];  // NEGATED H, same layout
static __device__ float  g_ct[NLAYERS][24];          // conv taps ct[i]=c[|i-KTAP|]
static __device__ float  g_scal[NLAYERS][8];

// ---------------------------------------------------------------------------
// packed f32x2 + warp helpers (sm_103a)
// ---------------------------------------------------------------------------
__device__ __forceinline__ float2 f2fma(float2 a, float2 b, float2 c) {
    unsigned long long ra = reinterpret_cast<unsigned long long&>(a);
    unsigned long long rb = reinterpret_cast<unsigned long long&>(b);
    unsigned long long rc = reinterpret_cast<unsigned long long&>(c);
    unsigned long long rd;
    asm("fma.rn.f32x2 %0, %1, %2, %3;" : "=l"(rd) : "l"(ra), "l"(rb), "l"(rc));
    return reinterpret_cast<float2&>(rd);
}
__device__ __forceinline__ float2 f2add(float2 a, float2 b) {
    unsigned long long ra = reinterpret_cast<unsigned long long&>(a);
    unsigned long long rb = reinterpret_cast<unsigned long long&>(b);
    unsigned long long rd;
    asm("add.rn.f32x2 %0, %1, %2;" : "=l"(rd) : "l"(ra), "l"(rb));
    return reinterpret_cast<float2&>(rd);
}
__device__ __forceinline__ float2 f2mul(float2 a, float2 b) {
    unsigned long long ra = reinterpret_cast<unsigned long long&>(a);
    unsigned long long rb = reinterpret_cast<unsigned long long&>(b);
    unsigned long long rd;
    asm("mul.rn.f32x2 %0, %1, %2;" : "=l"(rd) : "l"(ra), "l"(rb));
    return reinterpret_cast<float2&>(rd);
}
__device__ __forceinline__ float2 dup(float s) { return make_float2(s, s); }
__device__ __forceinline__ float2 shfl2(float2 v, int src) {
    float2 r;
    r.x = __shfl_sync(FULLMASK, v.x, src);
    r.y = __shfl_sync(FULLMASK, v.y, src);
    return r;
}
__device__ __forceinline__ float2 bfly_sum(float2 v) {
    #pragma unroll
    for (int off = 16; off >= 1; off >>= 1) {
        float sx = __shfl_xor_sync(FULLMASK, v.x, off);
        float sy = __shfl_xor_sync(FULLMASK, v.y, off);
        v = f2add(v, make_float2(sx, sy));
    }
    return v;
}
__device__ __forceinline__ float softt(float v, float lam) {
    return copysignf(fmaxf(fabsf(v) - lam, 0.f), v);
}

// ---------------------------------------------------------------------------
// Merged precompute, PARALLELIZED (runs every graph replay, so it matters):
//  - 4-way accumulators break the 300-long DFMA dependency chains
//  - G-loop reads a float smem copy of c (no per-iter double LDG + CVT)
//  - Gauss-Jordan: S9 = I + A C^-1 A^T is SPD -> no pivoting; 162-thread
//    parallel row ops (was serial on tid 0, ~3000 dependent double ops)
// Blocks 0..NLAYERS-1: per-layer tables. Block NLAYERS: A table.
// ---------------------------------------------------------------------------
__global__ void pre_all_kernel(const float* __restrict__ A,
                               const float* __restrict__ gamma_tv,
                               const float* __restrict__ lambda_tv,
                               const float* __restrict__ alpha) {
    int tid = threadIdx.x;

    if (blockIdx.x == NLAYERS) {
        for (int idx = tid; idx < NM * TBL12; idx += blockDim.x) {
            int m = idx / TBL12, ii = idx % TBL12;
            int L = ii / 12, t = ii % 12;
            int j = L * 10 + t;
            g_At[idx] = (t < 10 && j < N) ? A[m * N + j] : 0.0f;
        }
        return;
    }

    const double PI = 3.14159265358979323846;
    int l = blockIdx.x;
    double g = (double)gamma_tv[l], al = (double)alpha[l];

    __shared__ double costab[N];
    __shared__ double invlam[N];
    __shared__ float  cfl[N];
    for (int m = tid; m < N; m += blockDim.x) {
        double th = 2.0 * PI * (double)m / (double)N;
        costab[m] = cos(th);
        invlam[m] = 1.0 / (al + 2.0 * g - 2.0 * g * costab[m]);
    }
    __syncthreads();

    // c[k] with 4 accumulators (N divisible by 4)
    for (int k = tid; k < N; k += blockDim.x) {
        double s0 = 0.0, s1 = 0.0, s2 = 0.0, s3 = 0.0;
        int mk = 0;
        for (int m = 0; m < N; m += 4) {
            s0 += costab[mk] * invlam[m];     mk += k; if (mk >= N) mk -= N;
            s1 += costab[mk] * invlam[m + 1]; mk += k; if (mk >= N) mk -= N;
            s2 += costab[mk] * invlam[m + 2]; mk += k; if (mk >= N) mk -= N;
            s3 += costab[mk] * invlam[m + 3]; mk += k; if (mk >= N) mk -= N;
        }
        double c = ((s0 + s1) + (s2 + s3)) / (double)N;
        g_cfull[l][k] = c;
        cfl[k] = (float)c;
    }
    __syncthreads();

    // G[m][j] with float smem taps, 2 accumulators
    for (int idx = tid; idx < NM * N; idx += blockDim.x) {
        int m = idx / N, j = idx % N;
        float s0 = 0.f, s1 = 0.f;
        for (int t = 0; t < N; t += 2) {
            int d0 = j - t;       if (d0 < 0) d0 += N;
            int d1 = j - (t + 1); if (d1 < 0) d1 += N;
            s0 += A[m * N + t]     * cfl[d0];
            s1 += A[m * N + t + 1] * cfl[d1];
        }
        g_G[l][m * N + j] = s0 + s1;
    }
    __syncthreads();

    __shared__ double S9[81], S9i[81];
    for (int idx = tid; idx < 81; idx += blockDim.x) {
        int p = idx / 9, q = idx % 9;
        double s0 = 0.0, s1 = 0.0, s2 = 0.0, s3 = 0.0;
        for (int j = 0; j < N; j += 4) {
            s0 += (double)g_G[l][p * N + j]     * (double)A[q * N + j];
            s1 += (double)g_G[l][p * N + j + 1] * (double)A[q * N + j + 1];
            s2 += (double)g_G[l][p * N + j + 2] * (double)A[q * N + j + 2];
            s3 += (double)g_G[l][p * N + j + 3] * (double)A[q * N + j + 3];
        }
        double s = ((s0 + s1) + (s2 + s3));
        if (p == q) s += 1.0;
        S9[idx] = s;
        S9i[idx] = (p == q) ? 1.0 : 0.0;
    }
    __syncthreads();

    // Parallel Gauss-Jordan, no pivoting (S9 is SPD)
    __shared__ double dpiv;
    for (int col = 0; col < 9; col++) {
        if (tid == 0) dpiv = 1.0 / S9[col * 9 + col];
        __syncthreads();
        if (tid < 9)        S9 [col * 9 + tid]       *= dpiv;
        else if (tid < 18)  S9i[col * 9 + (tid - 9)] *= dpiv;
        __syncthreads();
        int r = tid / 18, c = tid % 18;
        bool act = (tid < 162) && (r != col);
        double f = act ? S9[r * 9 + col] : 0.0;
        __syncthreads();
        if (act) {
            if (c < 9) S9 [r * 9 + c]       -= f * S9 [col * 9 + c];
            else       S9i[r * 9 + (c - 9)] -= f * S9i[col * 9 + (c - 9)];
        }
        __syncthreads();
    }

    for (int idx = tid; idx < NM * TBL12; idx += blockDim.x) {
        int m = idx / TBL12, ii = idx % TBL12;
        int L = ii / 12, t = ii % 12;
        int j = L * 10 + t;
        float s = 0.f;
        if (t < 10 && j < N) {
            for (int q = 0; q < NM; q++)
                s -= (float)S9i[m * 9 + q] * g_G[l][q * N + j];
        }
        g_Hn[l][idx] = s;
    }
    for (int i = tid; i < 24; i += blockDim.x) {
        float v = 0.f;
        if (i < TAPS) { int d = i - KTAP; if (d < 0) d = -d; v = (float)g_cfull[l][d]; }
        g_ct[l][i] = v;
    }
    if (tid == 0) {
        g_scal[l][0] = (float)g;
        g_scal[l][1] = (float)al;
        g_scal[l][2] = (float)((double)lambda_tv[l] / g);
        g_scal[l][3] = (float)(1.0 / g);
        g_scal[l][4] = (float)(1.0 / al);
    }
}

// ---------------------------------------------------------------------------
// Main fused kernel: R12 structure (8 warps, state in registers, 1 block/SM,
// u/w cached per layer), conv at KTAP=9 (19 taps; pd from y keeps it
// self-consistent).
// Lane L (0..29) owns elements j = 10L..10L+9.
// ---------------------------------------------------------------------------
__global__ void __launch_bounds__(WARPS * 32)
ladmm_main(const float* __restrict__ b, float* __restrict__ out) {
    extern __shared__ float sm[];
    float*  sA    = sm;                                   // NM*TBL12      = 3456
    float*  sHn   = sA + NM * TBL12;                      // 5*NM*TBL12    = 17280
    float2* sct2  = (float2*)(sHn + NLAYERS * NM * TBL12);// 5*24 float2
    float*  sscal = (float*)(sct2 + NLAYERS * 24);        // 40
    float*  stage = sscal + 40;                           // WARPS*608

    int tid = threadIdx.x;
    for (int i = tid; i < NM * TBL12; i += WARPS * 32) sA[i] = g_At[i];
    for (int i = tid; i < NLAYERS * NM * TBL12; i += WARPS * 32) sHn[i] = (&g_Hn[0][0])[i];
    for (int i = tid; i < NLAYERS * 24; i += WARPS * 32) {
        float v = (&g_ct[0][0])[i];
        sct2[i] = make_float2(v, v);
    }
    for (int i = tid; i < NLAYERS * 8; i += WARPS * 32) sscal[i] = (&g_scal[0][0])[i];
    __syncthreads();

    int wid = tid >> 5, lane = tid & 31;
    int base12 = lane * 12;
    int j0 = lane * 10;
    int lm1 = (lane + 29) % 30;
    int lp1 = (lane + 1) % 30;

    const float2 neg1 = make_float2(-1.f, -1.f);
    float* wstage = stage + wid * 608;

    #pragma unroll 1
    for (int rit = 0; rit < RPW; rit++) {
        int pairIdx = blockIdx.x * (WARPS * RPW) + wid * RPW + rit;
        size_t row0 = (size_t)pairIdx * 2;

        // --- b rows -> bm[m] packed pairs
        float bv = (lane < 2 * NM) ? b[(size_t)pairIdx * (2 * NM) + lane] : 0.f;
        float2 bm[9];
        #pragma unroll
        for (int m = 0; m < 9; m++)
            bm[m] = make_float2(__shfl_sync(FULLMASK, bv, m),
                                __shfl_sync(FULLMASK, bv, 9 + m));

        // --- bA[t] = sum_m bm[m]*A[m][j0+t]  (m-outer, vector row loads)
        float2 bA[10];
        #pragma unroll
        for (int t = 0; t < 10; t++) bA[t] = make_float2(0.f, 0.f);
        #pragma unroll
        for (int m = 0; m < 9; m++) {
            const float4* rA = reinterpret_cast<const float4*>(sA + m * TBL12 + base12);
            float4 q0 = rA[0], q1 = rA[1], q2 = rA[2];
            float av[10] = {q0.x,q0.y,q0.z,q0.w,q1.x,q1.y,q1.z,q1.w,q2.x,q2.y};
            #pragma unroll
            for (int t = 0; t < 10; t++)
                bA[t] = f2fma(bm[m], dup(av[t]), bA[t]);
        }

        float2 x[10], eta[10], tau[10];
        #pragma unroll
        for (int t = 0; t < 10; t++) {
            x[t] = make_float2(1.f, 1.f);
            eta[t] = make_float2(0.f, 0.f);
            tau[t] = make_float2(0.f, 0.f);
        }

        #pragma unroll 1
        for (int l = 0; l < NLAYERS; l++) {
            const float* sc = sscal + l * 8;
            float gs = sc[0], als = sc[1], lamg = sc[2], invgs = sc[3], invals = sc[4];
            float2 g2 = dup(gs), al2 = dup(als), invg2 = dup(invgs), inval2 = dup(invals);
            const float2* ctab = sct2 + l * 24;
            const float* sHl = sHn + l * (NM * TBL12);

            // --- residual r = bA + al*w - tau + g*u - eta   (u,w kept live)
            float2 xm1 = shfl2(x[9], lm1);
            float2 r[10], uu[10], ww[10];
            #pragma unroll
            for (int t = 0; t < 10; t++) {
                float2 xp = (t == 0) ? xm1 : x[t - 1];
                float2 v = f2fma(neg1, x[t], xp);
                v = f2fma(eta[t], invg2, v);
                float2 u; u.x = softt(v.x, lamg); u.y = softt(v.y, lamg);
                float2 w = f2fma(tau[t], inval2, x[t]);
                w.x = fmaxf(w.x, 0.f); w.y = fmaxf(w.y, 0.f);
                uu[t] = u; ww[t] = w;
                float2 s = f2fma(neg1, tau[t], bA[t]);
                s = f2fma(al2, w, s);
                s = f2fma(g2, u, s);
                r[t] = f2fma(neg1, eta[t], s);
            }

            // --- y = C^-1 r : 19-tap circulant conv, ct[i] = c[|i-9|]
            float2 y[10];
            {
                float2 c9 = ctab[9];
                #pragma unroll
                for (int t = 0; t < 10; t++) y[t] = f2mul(c9, r[t]);
            }
            #pragma unroll
            for (int i = 0; i < 19; i++) {
                if (i == 9) continue;
                float2 ci = ctab[i];
                #pragma unroll
                for (int t = 0; t < 10; t++) {
                    int k = t + i - 9;
                    if (k >= 0 && k < 10) y[t] = f2fma(ci, r[k], y[t]);
                }
            }
            {
                // left halo: wm[k] = element j0-10+k (lane-1's r), k=1..9 used
                float2 wm[10];
                #pragma unroll
                for (int k = 1; k <= 9; k++) wm[k] = shfl2(r[k], lm1);
                #pragma unroll
                for (int i = 0; i < 9; i++) {
                    float2 ci = ctab[i];
                    #pragma unroll
                    for (int t = 0; t < 10; t++)
                        if (t + i < 9) y[t] = f2fma(ci, wm[t + i + 1], y[t]);
                }
            }
            {
                // right halo: wp[k] = element j0+10+k (lane+1's r), k=0..8 used
                float2 wp[10];
                #pragma unroll
                for (int k = 0; k <= 8; k++) wp[k] = shfl2(r[k], lp1);
                #pragma unroll
                for (int i = 10; i < 19; i++) {
                    float2 ci = ctab[i];
                    #pragma unroll
                    for (int t = 0; t < 10; t++)
                        if (t + i >= 19) y[t] = f2fma(ci, wp[t + i - 19], y[t]);
                }
            }

            // --- pd[m] = sum_j y_j A[m][j]  (m-outer vector loads + butterfly)
            float2 pd[9];
            #pragma unroll
            for (int m = 0; m < 9; m++) {
                const float4* rA = reinterpret_cast<const float4*>(sA + m * TBL12 + base12);
                float4 q0 = rA[0], q1 = rA[1], q2 = rA[2];
                float av[10] = {q0.x,q0.y,q0.z,q0.w,q1.x,q1.y,q1.z,q1.w,q2.x,q2.y};
                float2 acc = f2mul(y[0], dup(av[0]));
                #pragma unroll
                for (int t = 1; t < 10; t++)
                    acc = f2fma(y[t], dup(av[t]), acc);
                pd[m] = acc;
            }
            #pragma unroll
            for (int m = 0; m < 9; m++) pd[m] = bfly_sum(pd[m]);

            // --- xn = y + sum_m pd[m] * Hn[m][j]  (m-outer vector loads)
            float2 xn[10];
            #pragma unroll
            for (int t = 0; t < 10; t++) xn[t] = y[t];
            #pragma unroll
            for (int m = 0; m < 9; m++) {
                const float4* rH = reinterpret_cast<const float4*>(sHl + m * TBL12 + base12);
                float4 q0 = rH[0], q1 = rH[1], q2 = rH[2];
                float hv[10] = {q0.x,q0.y,q0.z,q0.w,q1.x,q1.y,q1.z,q1.w,q2.x,q2.y};
                #pragma unroll
                for (int t = 0; t < 10; t++)
                    xn[t] = f2fma(pd[m], dup(hv[t]), xn[t]);
            }

            // --- dual updates (u,w reused from residual phase)
            float2 xnm1 = shfl2(xn[9], lm1);
            #pragma unroll
            for (int t = 0; t < 10; t++) {
                float2 xnp = (t == 0) ? xnm1 : xn[t - 1];
                float2 d1 = f2fma(neg1, xn[t], xnp);
                d1 = f2fma(neg1, uu[t], d1);
                eta[t] = f2fma(g2, d1, eta[t]);
                float2 d2 = f2fma(neg1, ww[t], xn[t]);
                tau[t] = f2fma(al2, d2, tau[t]);
                x[t] = xn[t];
            }
        }

        // --- store both rows, coalesced float4 via smem staging
        __syncwarp();
        if (lane < 30) {
            #pragma unroll
            for (int t = 0; t < 10; t++) {
                wstage[j0 + t]       = x[t].x;
                wstage[304 + j0 + t] = x[t].y;
            }
        }
        __syncwarp();
        {
            const float4* st4 = reinterpret_cast<const float4*>(wstage);
            float4* out4 = reinterpret_cast<float4*>(out);
            size_t o0 = row0 * (N / 4);
            for (int idx = lane; idx < N / 4; idx += 32) {
                out4[o0 + idx] = st4[idx];
                out4[o0 + N / 4 + idx] = st4[76 + idx];
            }
        }
        __syncwarp();
    }
}

// ---------------------------------------------------------------------------
extern "C" void kernel_launch(void* const* d_in, const int* in_sizes, int n_in,
                              void* d_out, int out_size) {
    const float* b         = (const float*)d_in[0];
    const float* A         = (const float*)d_in[2];
    const float* gamma_tv  = (const float*)d_in[3];
    const float* lambda_tv = (const float*)d_in[4];
    const float* alpha     = (const float*)d_in[5];
    float* out = (float*)d_out;

    pre_all_kernel<<<NLAYERS + 1, 256>>>(A, gamma_tv, lambda_tv, alpha);

    size_t smembytes = (size_t)(NM * TBL12 * (1 + NLAYERS)            // 20736
                                + NLAYERS * 24 * 2 + NLAYERS * 8      // 280
                                + WARPS * 608) * sizeof(float);       // 4864 -> ~103KB
    cudaFuncSetAttribute(ladmm_main,
                         cudaFuncAttributeMaxDynamicSharedMemorySize,
                         (int)smembytes);
    int grid = NPAIRS / (WARPS * RPW);
    ladmm_main<<<grid, WARPS * 32, smembytes>>>(b, out);
}

// round 17
// speedup vs baseline: 1.8226x; 1.0346x over previous
#include <cuda_runtime.h>
#include <cstdint>
#include <math.h>

#define N       300
#define NM      9
#define BATCH   131072
#define NLAYERS 5
#define KTAP    9
#define TAPS    (2*KTAP + 1)   // 19
#define TBL12   384            // stride-12 table: row m at [m*384 + 12L + t]
#define WARPS   8
#define RPW     8              // row-PAIRS per warp
#define NPAIRS  (BATCH / 2)
#define FULLMASK 0xffffffffu

static __device__ double g_cfull[NLAYERS][N];
static __device__ float  g_G[NLAYERS][NM * N];
static __device__ float  g_At[NM * TBL12];           // A[m][j] fp32
static __device__ float  g_Hn[NLAYERS][NM * TBL12];  // NEGATED H fp32
static __device__ float  g_ct[NLAYERS][24];          // conv taps ct[i]=c[|i-KTAP|]
static __device__ float  g_scal[NLAYERS][8];

// ---------------------------------------------------------------------------
// packed f32x2 + warp helpers (sm_103a)
// ---------------------------------------------------------------------------
__device__ __forceinline__ float2 f2fma(float2 a, float2 b, float2 c) {
    unsigned long long ra = reinterpret_cast<unsigned long long&>(a);
    unsigned long long rb = reinterpret_cast<unsigned long long&>(b);
    unsigned long long rc = reinterpret_cast<unsigned long long&>(c);
    unsigned long long rd;
    asm("fma.rn.f32x2 %0, %1, %2, %3;" : "=l"(rd) : "l"(ra), "l"(rb), "l"(rc));
    return reinterpret_cast<float2&>(rd);
}
__device__ __forceinline__ float2 f2add(float2 a, float2 b) {
    unsigned long long ra = reinterpret_cast<unsigned long long&>(a);
    unsigned long long rb = reinterpret_cast<unsigned long long&>(b);
    unsigned long long rd;
    asm("add.rn.f32x2 %0, %1, %2;" : "=l"(rd) : "l"(ra), "l"(rb));
    return reinterpret_cast<float2&>(rd);
}
__device__ __forceinline__ float2 f2mul(float2 a, float2 b) {
    unsigned long long ra = reinterpret_cast<unsigned long long&>(a);
    unsigned long long rb = reinterpret_cast<unsigned long long&>(b);
    unsigned long long rd;
    asm("mul.rn.f32x2 %0, %1, %2;" : "=l"(rd) : "l"(ra), "l"(rb));
    return reinterpret_cast<float2&>(rd);
}
__device__ __forceinline__ float2 dup(float s) { return make_float2(s, s); }
__device__ __forceinline__ float2 shfl2(float2 v, int src) {
    float2 r;
    r.x = __shfl_sync(FULLMASK, v.x, src);
    r.y = __shfl_sync(FULLMASK, v.y, src);
    return r;
}
__device__ __forceinline__ float2 shflx2(float2 v, int mask) {
    float2 r;
    r.x = __shfl_xor_sync(FULLMASK, v.x, mask);
    r.y = __shfl_xor_sync(FULLMASK, v.y, mask);
    return r;
}
__device__ __forceinline__ float2 bfly_sum(float2 v) {
    #pragma unroll
    for (int off = 16; off >= 1; off >>= 1)
        v = f2add(v, shflx2(v, off));
    return v;
}
__device__ __forceinline__ float softt(float v, float lam) {
    return copysignf(fmaxf(fabsf(v) - lam, 0.f), v);
}

// ---------------------------------------------------------------------------
// Merged, parallelized precompute. Blocks 0..NLAYERS-1: per-layer tables.
// Block NLAYERS: A table.
// ---------------------------------------------------------------------------
__global__ void pre_all_kernel(const float* __restrict__ A,
                               const float* __restrict__ gamma_tv,
                               const float* __restrict__ lambda_tv,
                               const float* __restrict__ alpha) {
    int tid = threadIdx.x;

    if (blockIdx.x == NLAYERS) {
        for (int idx = tid; idx < NM * TBL12; idx += blockDim.x) {
            int m = idx / TBL12, ii = idx % TBL12;
            int L = ii / 12, t = ii % 12;
            int j = L * 10 + t;
            g_At[idx] = (t < 10 && j < N) ? A[m * N + j] : 0.0f;
        }
        return;
    }

    const double PI = 3.14159265358979323846;
    int l = blockIdx.x;
    double g = (double)gamma_tv[l], al = (double)alpha[l];

    __shared__ double costab[N];
    __shared__ double invlam[N];
    __shared__ float  cfl[N];
    for (int m = tid; m < N; m += blockDim.x) {
        double th = 2.0 * PI * (double)m / (double)N;
        costab[m] = cos(th);
        invlam[m] = 1.0 / (al + 2.0 * g - 2.0 * g * costab[m]);
    }
    __syncthreads();

    for (int k = tid; k < N; k += blockDim.x) {
        double s0 = 0.0, s1 = 0.0, s2 = 0.0, s3 = 0.0;
        int mk = 0;
        for (int m = 0; m < N; m += 4) {
            s0 += costab[mk] * invlam[m];     mk += k; if (mk >= N) mk -= N;
            s1 += costab[mk] * invlam[m + 1]; mk += k; if (mk >= N) mk -= N;
            s2 += costab[mk] * invlam[m + 2]; mk += k; if (mk >= N) mk -= N;
            s3 += costab[mk] * invlam[m + 3]; mk += k; if (mk >= N) mk -= N;
        }
        double c = ((s0 + s1) + (s2 + s3)) / (double)N;
        g_cfull[l][k] = c;
        cfl[k] = (float)c;
    }
    __syncthreads();

    for (int idx = tid; idx < NM * N; idx += blockDim.x) {
        int m = idx / N, j = idx % N;
        float s0 = 0.f, s1 = 0.f;
        for (int t = 0; t < N; t += 2) {
            int d0 = j - t;       if (d0 < 0) d0 += N;
            int d1 = j - (t + 1); if (d1 < 0) d1 += N;
            s0 += A[m * N + t]     * cfl[d0];
            s1 += A[m * N + t + 1] * cfl[d1];
        }
        g_G[l][m * N + j] = s0 + s1;
    }
    __syncthreads();

    __shared__ double S9[81], S9i[81];
    for (int idx = tid; idx < 81; idx += blockDim.x) {
        int p = idx / 9, q = idx % 9;
        double s0 = 0.0, s1 = 0.0, s2 = 0.0, s3 = 0.0;
        for (int j = 0; j < N; j += 4) {
            s0 += (double)g_G[l][p * N + j]     * (double)A[q * N + j];
            s1 += (double)g_G[l][p * N + j + 1] * (double)A[q * N + j + 1];
            s2 += (double)g_G[l][p * N + j + 2] * (double)A[q * N + j + 2];
            s3 += (double)g_G[l][p * N + j + 3] * (double)A[q * N + j + 3];
        }
        double s = ((s0 + s1) + (s2 + s3));
        if (p == q) s += 1.0;
        S9[idx] = s;
        S9i[idx] = (p == q) ? 1.0 : 0.0;
    }
    __syncthreads();

    // Parallel Gauss-Jordan, no pivoting (S9 is SPD)
    __shared__ double dpiv;
    for (int col = 0; col < 9; col++) {
        if (tid == 0) dpiv = 1.0 / S9[col * 9 + col];
        __syncthreads();
        if (tid < 9)        S9 [col * 9 + tid]       *= dpiv;
        else if (tid < 18)  S9i[col * 9 + (tid - 9)] *= dpiv;
        __syncthreads();
        int r = tid / 18, c = tid % 18;
        bool act = (tid < 162) && (r != col);
        double f = act ? S9[r * 9 + col] : 0.0;
        __syncthreads();
        if (act) {
            if (c < 9) S9 [r * 9 + c]       -= f * S9 [col * 9 + c];
            else       S9i[r * 9 + (c - 9)] -= f * S9i[col * 9 + (c - 9)];
        }
        __syncthreads();
    }

    for (int idx = tid; idx < NM * TBL12; idx += blockDim.x) {
        int m = idx / TBL12, ii = idx % TBL12;
        int L = ii / 12, t = ii % 12;
        int j = L * 10 + t;
        float s = 0.f;
        if (t < 10 && j < N) {
            for (int q = 0; q < NM; q++)
                s -= (float)S9i[m * 9 + q] * g_G[l][q * N + j];
        }
        g_Hn[l][idx] = s;
    }
    for (int i = tid; i < 24; i += blockDim.x) {
        float v = 0.f;
        if (i < TAPS) { int d = i - KTAP; if (d < 0) d = -d; v = (float)g_cfull[l][d]; }
        g_ct[l][i] = v;
    }
    if (tid == 0) {
        g_scal[l][0] = (float)g;
        g_scal[l][1] = (float)al;
        g_scal[l][2] = (float)((double)lambda_tv[l] / g);
        g_scal[l][3] = (float)(1.0 / g);
        g_scal[l][4] = (float)(1.0 / al);
    }
}

// ---------------------------------------------------------------------------
// Main fused kernel: 8 warps, register state, 1 block/SM, KTAP=9 conv,
// Hn fp32, multi-value butterfly (44 SHFL vs 90 for the 9 pd reductions),
// dual updates recompute u/w (lower regs, no spills).
// Lane L (0..29) owns elements j = 10L..10L+9.
// ---------------------------------------------------------------------------
__global__ void __launch_bounds__(WARPS * 32)
ladmm_main(const float* __restrict__ b, float* __restrict__ out) {
    extern __shared__ float sm[];
    float*  sA    = sm;                                   // NM*TBL12
    float*  sHn   = sA + NM * TBL12;                      // 5*NM*TBL12
    float2* sct2  = (float2*)(sHn + NLAYERS * NM * TBL12);// 5*24 float2
    float*  sscal = (float*)(sct2 + NLAYERS * 24);        // 40
    float*  stage = sscal + 40;                           // WARPS*608

    int tid = threadIdx.x;
    for (int i = tid; i < NM * TBL12; i += WARPS * 32) sA[i] = g_At[i];
    for (int i = tid; i < NLAYERS * NM * TBL12; i += WARPS * 32) sHn[i] = (&g_Hn[0][0])[i];
    for (int i = tid; i < NLAYERS * 24; i += WARPS * 32) {
        float v = (&g_ct[0][0])[i];
        sct2[i] = make_float2(v, v);
    }
    for (int i = tid; i < NLAYERS * 8; i += WARPS * 32) sscal[i] = (&g_scal[0][0])[i];
    __syncthreads();

    int wid = tid >> 5, lane = tid & 31;
    int base12 = lane * 12;
    int j0 = lane * 10;
    int lm1 = (lane + 29) % 30;
    int lp1 = (lane + 1) % 30;
    bool b16 = (lane & 16) != 0;
    bool b8  = (lane & 8) != 0;
    bool b4  = (lane & 4) != 0;

    const float2 neg1 = make_float2(-1.f, -1.f);
    float* wstage = stage + wid * 608;

    #pragma unroll 1
    for (int rit = 0; rit < RPW; rit++) {
        int pairIdx = blockIdx.x * (WARPS * RPW) + wid * RPW + rit;
        size_t row0 = (size_t)pairIdx * 2;

        // --- b rows -> bm[m] packed pairs
        float bv = (lane < 2 * NM) ? b[(size_t)pairIdx * (2 * NM) + lane] : 0.f;
        float2 bm[9];
        #pragma unroll
        for (int m = 0; m < 9; m++)
            bm[m] = make_float2(__shfl_sync(FULLMASK, bv, m),
                                __shfl_sync(FULLMASK, bv, 9 + m));

        // --- bA[t] = sum_m bm[m]*A[m][j0+t]
        float2 bA[10];
        #pragma unroll
        for (int t = 0; t < 10; t++) bA[t] = make_float2(0.f, 0.f);
        #pragma unroll
        for (int m = 0; m < 9; m++) {
            const float4* rA = reinterpret_cast<const float4*>(sA + m * TBL12 + base12);
            float4 q0 = rA[0], q1 = rA[1], q2 = rA[2];
            float av[10] = {q0.x,q0.y,q0.z,q0.w,q1.x,q1.y,q1.z,q1.w,q2.x,q2.y};
            #pragma unroll
            for (int t = 0; t < 10; t++)
                bA[t] = f2fma(bm[m], dup(av[t]), bA[t]);
        }

        float2 x[10], eta[10], tau[10];
        #pragma unroll
        for (int t = 0; t < 10; t++) {
            x[t] = make_float2(1.f, 1.f);
            eta[t] = make_float2(0.f, 0.f);
            tau[t] = make_float2(0.f, 0.f);
        }

        #pragma unroll 1
        for (int l = 0; l < NLAYERS; l++) {
            const float* sc = sscal + l * 8;
            float gs = sc[0], als = sc[1], lamg = sc[2], invgs = sc[3], invals = sc[4];
            float2 g2 = dup(gs), al2 = dup(als), invg2 = dup(invgs), inval2 = dup(invals);
            const float2* ctab = sct2 + l * 24;
            const float* sHl = sHn + l * (NM * TBL12);

            // --- residual r = bA + al*w - tau + g*u - eta
            float2 xm1 = shfl2(x[9], lm1);
            float2 r[10];
            #pragma unroll
            for (int t = 0; t < 10; t++) {
                float2 xp = (t == 0) ? xm1 : x[t - 1];
                float2 v = f2fma(neg1, x[t], xp);
                v = f2fma(eta[t], invg2, v);
                float2 u; u.x = softt(v.x, lamg); u.y = softt(v.y, lamg);
                float2 w = f2fma(tau[t], inval2, x[t]);
                w.x = fmaxf(w.x, 0.f); w.y = fmaxf(w.y, 0.f);
                float2 s = f2fma(neg1, tau[t], bA[t]);
                s = f2fma(al2, w, s);
                s = f2fma(g2, u, s);
                r[t] = f2fma(neg1, eta[t], s);
            }

            // --- y = C^-1 r : 19-tap circulant conv, ct[i] = c[|i-9|]
            float2 y[10];
            {
                float2 c9 = ctab[9];
                #pragma unroll
                for (int t = 0; t < 10; t++) y[t] = f2mul(c9, r[t]);
            }
            #pragma unroll
            for (int i = 0; i < 19; i++) {
                if (i == 9) continue;
                float2 ci = ctab[i];
                #pragma unroll
                for (int t = 0; t < 10; t++) {
                    int k = t + i - 9;
                    if (k >= 0 && k < 10) y[t] = f2fma(ci, r[k], y[t]);
                }
            }
            {
                float2 wm[10];
                #pragma unroll
                for (int k = 1; k <= 9; k++) wm[k] = shfl2(r[k], lm1);
                #pragma unroll
                for (int i = 0; i < 9; i++) {
                    float2 ci = ctab[i];
                    #pragma unroll
                    for (int t = 0; t < 10; t++)
                        if (t + i < 9) y[t] = f2fma(ci, wm[t + i + 1], y[t]);
                }
            }
            {
                float2 wp[10];
                #pragma unroll
                for (int k = 0; k <= 8; k++) wp[k] = shfl2(r[k], lp1);
                #pragma unroll
                for (int i = 10; i < 19; i++) {
                    float2 ci = ctab[i];
                    #pragma unroll
                    for (int t = 0; t < 10; t++)
                        if (t + i >= 19) y[t] = f2fma(ci, wp[t + i - 19], y[t]);
                }
            }

            // --- pd[m] = sum_j y_j A[m][j]  (m-outer vector loads)
            float2 pd[9];
            #pragma unroll
            for (int m = 0; m < 9; m++) {
                const float4* rA = reinterpret_cast<const float4*>(sA + m * TBL12 + base12);
                float4 q0 = rA[0], q1 = rA[1], q2 = rA[2];
                float av[10] = {q0.x,q0.y,q0.z,q0.w,q1.x,q1.y,q1.z,q1.w,q2.x,q2.y};
                float2 acc = f2mul(y[0], dup(av[0]));
                #pragma unroll
                for (int t = 1; t < 10; t++)
                    acc = f2fma(y[t], dup(av[t]), acc);
                pd[m] = acc;
            }

            // --- multi-value butterfly for pd[0..7] (44 SHFL total vs 90):
            //     xor16/8/4 split-exchange leaves pd[m] at lanes (lane>>2)&7==m,
            //     xor2/xor1 finish, broadcast from lane 4m. pd[8] classic.
            {
                float2 v0, v1, v2, v3;
                {
                    float2 k0 = b16 ? pd[4] : pd[0], g0 = b16 ? pd[0] : pd[4];
                    float2 k1 = b16 ? pd[5] : pd[1], g1 = b16 ? pd[1] : pd[5];
                    float2 k2 = b16 ? pd[6] : pd[2], g2x = b16 ? pd[2] : pd[6];
                    float2 k3 = b16 ? pd[7] : pd[3], g3 = b16 ? pd[3] : pd[7];
                    v0 = f2add(k0, shflx2(g0, 16));
                    v1 = f2add(k1, shflx2(g1, 16));
                    v2 = f2add(k2, shflx2(g2x, 16));
                    v3 = f2add(k3, shflx2(g3, 16));
                }
                float2 u0, u1;
                {
                    float2 k0 = b8 ? v2 : v0, g0 = b8 ? v0 : v2;
                    float2 k1 = b8 ? v3 : v1, g1 = b8 ? v1 : v3;
                    u0 = f2add(k0, shflx2(g0, 8));
                    u1 = f2add(k1, shflx2(g1, 8));
                }
                float2 wv;
                {
                    float2 k0 = b4 ? u1 : u0, g0 = b4 ? u0 : u1;
                    wv = f2add(k0, shflx2(g0, 4));
                }
                wv = f2add(wv, shflx2(wv, 2));
                wv = f2add(wv, shflx2(wv, 1));
                #pragma unroll
                for (int m = 0; m < 8; m++) pd[m] = shfl2(wv, 4 * m);
                pd[8] = bfly_sum(pd[8]);
            }

            // --- xn = y + sum_m pd[m] * Hn[m][j]
            float2 xn[10];
            #pragma unroll
            for (int t = 0; t < 10; t++) xn[t] = y[t];
            #pragma unroll
            for (int m = 0; m < 9; m++) {
                const float4* rH = reinterpret_cast<const float4*>(sHl + m * TBL12 + base12);
                float4 q0 = rH[0], q1 = rH[1], q2 = rH[2];
                float hv[10] = {q0.x,q0.y,q0.z,q0.w,q1.x,q1.y,q1.z,q1.w,q2.x,q2.y};
                #pragma unroll
                for (int t = 0; t < 10; t++)
                    xn[t] = f2fma(pd[m], dup(hv[t]), xn[t]);
            }

            // --- dual updates (recompute u,w from OLD state)
            float2 xnm1 = shfl2(xn[9], lm1);
            float2 xprev_old = xm1;
            #pragma unroll
            for (int t = 0; t < 10; t++) {
                float2 xp = xprev_old;
                xprev_old = x[t];
                float2 xnp = (t == 0) ? xnm1 : xn[t - 1];
                float2 v = f2fma(neg1, x[t], xp);
                v = f2fma(eta[t], invg2, v);
                float2 u; u.x = softt(v.x, lamg); u.y = softt(v.y, lamg);
                float2 w = f2fma(tau[t], inval2, x[t]);
                w.x = fmaxf(w.x, 0.f); w.y = fmaxf(w.y, 0.f);
                float2 d1 = f2fma(neg1, xn[t], xnp);
                d1 = f2fma(neg1, u, d1);
                eta[t] = f2fma(g2, d1, eta[t]);
                float2 d2 = f2fma(neg1, w, xn[t]);
                tau[t] = f2fma(al2, d2, tau[t]);
                x[t] = xn[t];
            }
        }

        // --- store both rows, coalesced float4 via smem staging
        __syncwarp();
        if (lane < 30) {
            #pragma unroll
            for (int t = 0; t < 10; t++) {
                wstage[j0 + t]       = x[t].x;
                wstage[304 + j0 + t] = x[t].y;
            }
        }
        __syncwarp();
        {
            const float4* st4 = reinterpret_cast<const float4*>(wstage);
            float4* out4 = reinterpret_cast<float4*>(out);
            size_t o0 = row0 * (N / 4);
            for (int idx = lane; idx < N / 4; idx += 32) {
                out4[o0 + idx] = st4[idx];
                out4[o0 + N / 4 + idx] = st4[76 + idx];
            }
        }
        __syncwarp();
    }
}

// ---------------------------------------------------------------------------
extern "C" void kernel_launch(void* const* d_in, const int* in_sizes, int n_in,
                              void* d_out, int out_size) {
    const float* b         = (const float*)d_in[0];
    const float* A         = (const float*)d_in[2];
    const float* gamma_tv  = (const float*)d_in[3];
    const float* lambda_tv = (const float*)d_in[4];
    const float* alpha     = (const float*)d_in[5];
    float* out = (float*)d_out;

    pre_all_kernel<<<NLAYERS + 1, 256>>>(A, gamma_tv, lambda_tv, alpha);

    size_t smembytes = (size_t)(NM * TBL12 * (1 + NLAYERS)            // 20736
                                + NLAYERS * 24 * 2 + NLAYERS * 8      // 280
                                + WARPS * 608) * sizeof(float);       // 4864 -> ~103KB
    cudaFuncSetAttribute(ladmm_main,
                         cudaFuncAttributeMaxDynamicSharedMemorySize,
                         (int)smembytes);
    int grid = NPAIRS / (WARPS * RPW);
    ladmm_main<<<grid, WARPS * 32, smembytes>>>(b, out);
}